// round 1
// baseline (speedup 1.0000x reference)
#include <cuda_runtime.h>
#include <cuda_bf16.h>
#include <math.h>

#define BATCH 4
#define TLEN  4096
#define DIM   768
#define NSEL  256
#define HID   200
#define NPAIR 32640          // NSEL*(NSEL-1)/2
#define PB    40             // pairs per block in MLP kernels
#define NBLK  816            // NPAIR / PB

// ---------------- device scratch (static, allocation-free) ----------------
__device__ float g_E [BATCH * NSEL * DIM];          // gathered embeddings
__device__ float g_AB[BATCH * NSEL * 2 * HID];      // per-token A/B partials
__device__ float g_H1[(size_t)BATCH * NPAIR * HID]; // layer-1 activations (~104 MB)
__device__ float g_S [BATCH * NSEL * NSEL];         // pair scores (strict lower tri)
__device__ int   g_II[NPAIR];
__device__ int   g_JJ[NPAIR];

// ---------------- pair index table ----------------
__global__ void k_pairs() {
    int p = blockIdx.x * blockDim.x + threadIdx.x;
    if (p >= NPAIR) return;
    int i = (int)((1.0f + sqrtf(1.0f + 8.0f * (float)p)) * 0.5f);
    while (i > 1 && i * (i - 1) / 2 > p) --i;
    while ((i + 1) * i / 2 <= p) ++i;
    g_II[p] = i;
    g_JJ[p] = p - i * (i - 1) / 2;
}

// ---------------- gather ----------------
__global__ void k_gather(const float* __restrict__ emb, const int* __restrict__ idx) {
    int bn = blockIdx.x;                 // 0 .. BATCH*NSEL-1
    int b = bn / NSEL, n = bn % NSEL;
    int t = idx[b * NSEL + n];
    const float4* src = (const float4*)(emb + ((size_t)b * TLEN + t) * DIM);
    float4* dst = (float4*)(g_E + (size_t)bn * DIM);
    for (int d = threadIdx.x; d < DIM / 4; d += blockDim.x) dst[d] = src[d];
}

// ---------------- A/B partials: g_AB[row][c] = sum_d E[row][d] * W1[(c/200)*768+d][c%200]
// M=1024, K=768, Ncols=400.  BM=64, BN=64, BK=16, 256 thr, 4x4 per thread.
__global__ void k_ab(const float* __restrict__ W1) {
    __shared__ __align__(16) float As[16][64 + 4];
    __shared__ __align__(16) float Bs[16][64 + 4];
    int bm = blockIdx.x * 64, bn = blockIdx.y * 64;
    int tx = threadIdx.x % 16, ty = threadIdx.x / 16;
    float acc[4][4] = {};
    for (int k0 = 0; k0 < DIM; k0 += 16) {
        for (int t = threadIdx.x; t < 1024; t += 256) {
            int k = t % 16, m = t / 16;
            As[k][m] = g_E[(size_t)(bm + m) * DIM + k0 + k];
        }
        for (int t = threadIdx.x; t < 1024; t += 256) {
            int n = t % 64, k = t / 64;
            int c = bn + n;
            float v = 0.f;
            if (c < 2 * HID) {
                int half = c / HID, h = c - half * HID;
                v = W1[(size_t)(half * DIM + k0 + k) * HID + h];
            }
            Bs[k][n] = v;
        }
        __syncthreads();
        #pragma unroll
        for (int k = 0; k < 16; ++k) {
            float a[4], bb[4];
            #pragma unroll
            for (int u = 0; u < 4; ++u) a[u] = As[k][ty * 4 + u];
            #pragma unroll
            for (int v = 0; v < 4; ++v) bb[v] = Bs[k][tx * 4 + v];
            #pragma unroll
            for (int u = 0; u < 4; ++u)
                #pragma unroll
                for (int v = 0; v < 4; ++v)
                    acc[u][v] = fmaf(a[u], bb[v], acc[u][v]);
        }
        __syncthreads();
    }
    #pragma unroll
    for (int u = 0; u < 4; ++u)
        #pragma unroll
        for (int v = 0; v < 4; ++v) {
            int c = bn + tx * 4 + v;
            if (c < 2 * HID)
                g_AB[(size_t)(bm + ty * 4 + u) * (2 * HID) + c] = acc[u][v];
        }
}

// ---------------- layer 1 (product term) + bias + relu ----------------
// C[p][h] = sum_d (E_i[d]*E_j[d]) * W1c[d][h];  M = 40 pairs/blk, N = 200, K = 768
// 250 active threads: pt in [0,10) x ht in [0,25); thread tile 4 pairs x 8 h.
__global__ void k_mlp1(const float* __restrict__ W1, const float* __restrict__ b1) {
    __shared__ __align__(16) float Ws[16][HID];
    __shared__ __align__(16) float Xs[16][PB];
    __shared__ int sII[PB], sJJ[PB];
    int b  = blockIdx.y;
    int p0 = blockIdx.x * PB;
    int tid = threadIdx.x;
    if (tid < PB) { sII[tid] = g_II[p0 + tid]; sJJ[tid] = g_JJ[p0 + tid]; }
    __syncthreads();
    const float* Eb = g_E + (size_t)b * NSEL * DIM;
    int pt = tid / 25, ht = tid % 25;
    bool active = tid < 250;
    float acc[4][8] = {};
    for (int k0 = 0; k0 < DIM; k0 += 16) {
        for (int t = tid; t < 16 * HID; t += 256) {
            int h = t % HID, k = t / HID;
            Ws[k][h] = W1[(size_t)(2 * DIM + k0 + k) * HID + h];
        }
        for (int t = tid; t < 16 * PB; t += 256) {
            int k = t % 16, pp = t / 16;
            Xs[k][pp] = Eb[(size_t)sII[pp] * DIM + k0 + k] *
                        Eb[(size_t)sJJ[pp] * DIM + k0 + k];
        }
        __syncthreads();
        if (active) {
            #pragma unroll
            for (int k = 0; k < 16; ++k) {
                float4 xv = *(const float4*)&Xs[k][pt * 4];
                float4 w0 = *(const float4*)&Ws[k][ht * 8];
                float4 w1 = *(const float4*)&Ws[k][ht * 8 + 4];
                float x[4] = {xv.x, xv.y, xv.z, xv.w};
                float w[8] = {w0.x, w0.y, w0.z, w0.w, w1.x, w1.y, w1.z, w1.w};
                #pragma unroll
                for (int u = 0; u < 4; ++u)
                    #pragma unroll
                    for (int v = 0; v < 8; ++v)
                        acc[u][v] = fmaf(x[u], w[v], acc[u][v]);
            }
        }
        __syncthreads();
    }
    if (active) {
        #pragma unroll
        for (int u = 0; u < 4; ++u) {
            int pp = pt * 4 + u;
            int i = sII[pp], j = sJJ[pp];
            const float* Ai = g_AB + (size_t)(b * NSEL + i) * (2 * HID);
            const float* Bj = g_AB + (size_t)(b * NSEL + j) * (2 * HID) + HID;
            float* H = g_H1 + ((size_t)b * NPAIR + p0 + pp) * HID;
            #pragma unroll
            for (int v = 0; v < 8; ++v) {
                int h = ht * 8 + v;
                float val = acc[u][v] + Ai[h] + Bj[h] + b1[h];
                H[h] = fmaxf(val, 0.f);
            }
        }
    }
}

// ---------------- layer 2 + relu + layer 3 dot, scatter into S ----------------
__global__ void k_mlp2(const float* __restrict__ W2, const float* __restrict__ b2,
                       const float* __restrict__ W3, const float* __restrict__ b3) {
    __shared__ __align__(16) float Ws[20][HID];
    __shared__ __align__(16) float Xs[20][PB];
    __shared__ float sred[25][PB];
    int b  = blockIdx.y;
    int p0 = blockIdx.x * PB;
    int tid = threadIdx.x;
    int pt = tid / 25, ht = tid % 25;
    bool active = tid < 250;
    float acc[4][8] = {};
    for (int k0 = 0; k0 < HID; k0 += 20) {
        for (int t = tid; t < 20 * HID; t += 256) {
            int h = t % HID, k = t / HID;
            Ws[k][h] = W2[(size_t)(k0 + k) * HID + h];
        }
        for (int t = tid; t < 20 * PB; t += 256) {
            int k = t % 20, pp = t / 20;
            Xs[k][pp] = g_H1[((size_t)b * NPAIR + p0 + pp) * HID + k0 + k];
        }
        __syncthreads();
        if (active) {
            #pragma unroll
            for (int k = 0; k < 20; ++k) {
                float4 xv = *(const float4*)&Xs[k][pt * 4];
                float4 w0 = *(const float4*)&Ws[k][ht * 8];
                float4 w1 = *(const float4*)&Ws[k][ht * 8 + 4];
                float x[4] = {xv.x, xv.y, xv.z, xv.w};
                float w[8] = {w0.x, w0.y, w0.z, w0.w, w1.x, w1.y, w1.z, w1.w};
                #pragma unroll
                for (int u = 0; u < 4; ++u)
                    #pragma unroll
                    for (int v = 0; v < 8; ++v)
                        acc[u][v] = fmaf(x[u], w[v], acc[u][v]);
            }
        }
        __syncthreads();
    }
    if (active) {
        #pragma unroll
        for (int u = 0; u < 4; ++u) {
            float sp = 0.f;
            #pragma unroll
            for (int v = 0; v < 8; ++v) {
                int h = ht * 8 + v;
                float h2 = fmaxf(acc[u][v] + b2[h], 0.f);
                sp = fmaf(h2, W3[h], sp);
            }
            sred[ht][pt * 4 + u] = sp;
        }
    }
    __syncthreads();
    if (tid < PB) {
        float s = 0.f;
        #pragma unroll
        for (int r = 0; r < 25; ++r) s += sred[r][tid];
        s += b3[0];
        int p = p0 + tid;
        int i = g_II[p], j = g_JJ[p];
        g_S[((size_t)b * NSEL + i) * NSEL + j] = s;
    }
}

// ---------------- row softmax + fill ----------------
__global__ void k_soft(float* __restrict__ out) {
    int bn = blockIdx.x;
    int i = bn % NSEL;
    const float* Srow = g_S + (size_t)bn * NSEL;
    float* orow = out + (size_t)bn * NSEL;
    __shared__ float red[256];
    int tid = threadIdx.x;

    float mx = -1e30f;
    for (int j = tid; j <= i; j += 256) {
        float l = (j == i) ? 0.f : Srow[j];
        mx = fmaxf(mx, l);
    }
    red[tid] = mx; __syncthreads();
    for (int s = 128; s > 0; s >>= 1) {
        if (tid < s) red[tid] = fmaxf(red[tid], red[tid + s]);
        __syncthreads();
    }
    mx = red[0]; __syncthreads();

    float sum = 0.f;
    for (int j = tid; j <= i; j += 256) {
        float l = (j == i) ? 0.f : Srow[j];
        sum += __expf(l - mx);
    }
    red[tid] = sum; __syncthreads();
    for (int s = 128; s > 0; s >>= 1) {
        if (tid < s) red[tid] += red[tid + s];
        __syncthreads();
    }
    sum = red[0];
    float inv = 1.0f / sum;

    for (int j = tid; j < NSEL; j += 256) {
        if (j <= i) {
            float l = (j == i) ? 0.f : Srow[j];
            orow[j] = __expf(l - mx) * inv;
        } else {
            orow[j] = -1000.0f;
        }
    }
}

// ---------------- launch ----------------
extern "C" void kernel_launch(void* const* d_in, const int* in_sizes, int n_in,
                              void* d_out, int out_size) {
    const float* emb = (const float*)d_in[0];
    const int*   idx = (const int*)  d_in[1];
    const float* W1  = (const float*)d_in[2];
    const float* b1  = (const float*)d_in[3];
    const float* W2  = (const float*)d_in[4];
    const float* b2  = (const float*)d_in[5];
    const float* W3  = (const float*)d_in[6];
    const float* b3  = (const float*)d_in[7];
    float* out = (float*)d_out;

    k_pairs<<<(NPAIR + 255) / 256, 256>>>();
    k_gather<<<BATCH * NSEL, 192>>>(emb, idx);
    k_ab<<<dim3(16, 7), 256>>>(W1);
    k_mlp1<<<dim3(NBLK, BATCH), 256>>>(W1, b1);
    k_mlp2<<<dim3(NBLK, BATCH), 256>>>(W2, b2, W3, b3);
    k_soft<<<BATCH * NSEL, 256>>>(out);
}

// round 3
// speedup vs baseline: 2.8282x; 2.8282x over previous
#include <cuda_runtime.h>
#include <cuda_bf16.h>
#include <math.h>
#include <stdint.h>

#define BATCH 4
#define TLEN  4096
#define DIM   768
#define NSEL  256
#define HID   200
#define NPAIR 32640          // NSEL*(NSEL-1)/2
#define MTILE 128            // pairs per CTA
#define NPAD  256            // padded hidden (cols 200..255 zero-weight)
#define NT1   255            // NPAIR / MTILE
#define K2PAD 256            // padded K for layer 2
#define XS_STRIDE 40         // bf16 elems per smem row (80B -> conflict-free frags)

// ---------------- device scratch ----------------
__device__ float          g_E  [BATCH * NSEL * DIM];
__device__ float          g_AB [BATCH * NSEL * 2 * HID];
__device__ __nv_bfloat16  g_W1t[NPAD * DIM];                  // [h][d], rows>=200 zero
__device__ __nv_bfloat16  g_W2t[NPAD * K2PAD];                // [h][k], pads zero
__device__ __nv_bfloat16  g_H1 [(size_t)BATCH * NPAIR * K2PAD]; // pad cols never written (stay 0)
__device__ float          g_S  [BATCH * NSEL * NSEL];
__device__ int            g_II [NPAIR];
__device__ int            g_JJ [NPAIR];

// ---------------- mma helper ----------------
__device__ __forceinline__ void mma16816(float* c, const uint32_t* a, const uint32_t* b) {
    asm volatile(
        "mma.sync.aligned.m16n8k16.row.col.f32.bf16.bf16.f32 "
        "{%0,%1,%2,%3}, {%4,%5,%6,%7}, {%8,%9}, {%0,%1,%2,%3};"
        : "+f"(c[0]), "+f"(c[1]), "+f"(c[2]), "+f"(c[3])
        : "r"(a[0]), "r"(a[1]), "r"(a[2]), "r"(a[3]), "r"(b[0]), "r"(b[1]));
}
__device__ __forceinline__ uint32_t lds_u32(const __nv_bfloat16* base, int elem_off) {
    return *(const uint32_t*)((const char*)base + elem_off * 2);
}

// ---------------- pair index table ----------------
__global__ void k_pairs() {
    int p = blockIdx.x * blockDim.x + threadIdx.x;
    if (p >= NPAIR) return;
    int i = (int)((1.0f + sqrtf(1.0f + 8.0f * (float)p)) * 0.5f);
    while (i > 1 && i * (i - 1) / 2 > p) --i;
    while ((i + 1) * i / 2 <= p) ++i;
    g_II[p] = i;
    g_JJ[p] = p - i * (i - 1) / 2;
}

// ---------------- gather ----------------
__global__ void k_gather(const float* __restrict__ emb, const int* __restrict__ idx) {
    int bn = blockIdx.x;
    int b = bn / NSEL, n = bn % NSEL;
    int t = idx[b * NSEL + n];
    const float4* src = (const float4*)(emb + ((size_t)b * TLEN + t) * DIM);
    float4* dst = (float4*)(g_E + (size_t)bn * DIM);
    for (int d = threadIdx.x; d < DIM / 4; d += blockDim.x) dst[d] = src[d];
}

// ---------------- weight transposes (bf16, K-major, zero-padded) ----------------
__global__ void k_w1t(const float* __restrict__ W1) {
    int e = blockIdx.x * blockDim.x + threadIdx.x;
    if (e >= NPAD * DIM) return;
    int h = e / DIM, d = e % DIM;
    float v = (h < HID) ? W1[(size_t)(2 * DIM + d) * HID + h] : 0.f;
    g_W1t[e] = __float2bfloat16(v);
}
__global__ void k_w2t(const float* __restrict__ W2) {
    int e = blockIdx.x * blockDim.x + threadIdx.x;
    if (e >= NPAD * K2PAD) return;
    int h = e / K2PAD, k = e % K2PAD;
    float v = (h < HID && k < HID) ? W2[(size_t)k * HID + h] : 0.f;
    g_W2t[e] = __float2bfloat16(v);
}

// ---------------- exact A/B partials (fp32 SIMT, small) ----------------
__global__ void k_ab(const float* __restrict__ W1) {
    __shared__ __align__(16) float As[16][64 + 4];
    __shared__ __align__(16) float Bs[16][64 + 4];
    int bm = blockIdx.x * 64, bn = blockIdx.y * 64;
    int tx = threadIdx.x % 16, ty = threadIdx.x / 16;
    float acc[4][4] = {};
    for (int k0 = 0; k0 < DIM; k0 += 16) {
        for (int t = threadIdx.x; t < 1024; t += 256) {
            int k = t % 16, m = t / 16;
            As[k][m] = g_E[(size_t)(bm + m) * DIM + k0 + k];
        }
        for (int t = threadIdx.x; t < 1024; t += 256) {
            int n = t % 64, k = t / 64;
            int c = bn + n;
            float v = 0.f;
            if (c < 2 * HID) {
                int half = c / HID, h = c - half * HID;
                v = W1[(size_t)(half * DIM + k0 + k) * HID + h];
            }
            Bs[k][n] = v;
        }
        __syncthreads();
        #pragma unroll
        for (int k = 0; k < 16; ++k) {
            float a[4], bb[4];
            #pragma unroll
            for (int u = 0; u < 4; ++u) a[u] = As[k][ty * 4 + u];
            #pragma unroll
            for (int v = 0; v < 4; ++v) bb[v] = Bs[k][tx * 4 + v];
            #pragma unroll
            for (int u = 0; u < 4; ++u)
                #pragma unroll
                for (int v = 0; v < 4; ++v)
                    acc[u][v] = fmaf(a[u], bb[v], acc[u][v]);
        }
        __syncthreads();
    }
    #pragma unroll
    for (int u = 0; u < 4; ++u)
        #pragma unroll
        for (int v = 0; v < 4; ++v) {
            int c = bn + tx * 4 + v;
            if (c < 2 * HID)
                g_AB[(size_t)(bm + ty * 4 + u) * (2 * HID) + c] = acc[u][v];
        }
}

// ================= layer 1: mma.sync bf16 GEMM (+exact partials, relu) =================
// CTA: 128 pairs x 256 hid(pad), K=768 in 24 chunks of 32.
// 8 warps as (wm=wid&1)x(wn=wid>>1): warp tile 64x64.
__global__ __launch_bounds__(256)
void k_l1(const float* __restrict__ b1) {
    __shared__ __nv_bfloat16 Xs[MTILE * XS_STRIDE];
    __shared__ __nv_bfloat16 Ws[NPAD  * XS_STRIDE];
    __shared__ float b1s[HID];
    __shared__ int sII[MTILE], sJJ[MTILE];

    int tid = threadIdx.x;
    int b = blockIdx.y;
    int p0 = blockIdx.x * MTILE;
    if (tid < MTILE) { sII[tid] = g_II[p0 + tid]; sJJ[tid] = g_JJ[p0 + tid]; }
    if (tid < HID) b1s[tid] = b1[tid];
    __syncthreads();

    const float* Eb = g_E + (size_t)b * NSEL * DIM;
    int wid = tid / 32, lane = tid % 32;
    int wm = wid & 1, wn = wid >> 1;
    int q = lane >> 2, l4 = lane & 3;

    float acc[4][8][4];
    #pragma unroll
    for (int mt = 0; mt < 4; ++mt)
        #pragma unroll
        for (int nt = 0; nt < 8; ++nt)
            #pragma unroll
            for (int v = 0; v < 4; ++v) acc[mt][nt][v] = 0.f;

    for (int c = 0; c < DIM / 32; ++c) {
        int c0 = c * 32;
        // X: 128 x 32 products -> bf16
        for (int e = tid; e < MTILE * 16; e += 256) {
            int r = e >> 4, kk = (e & 15) * 2;
            const float2 xi = *(const float2*)(Eb + (size_t)sII[r] * DIM + c0 + kk);
            const float2 xj = *(const float2*)(Eb + (size_t)sJJ[r] * DIM + c0 + kk);
            __nv_bfloat162 v = __floats2bfloat162_rn(xi.x * xj.x, xi.y * xj.y);
            *(uint32_t*)&Xs[r * XS_STRIDE + kk] = *(uint32_t*)&v;
        }
        // W: 256 x 32
        for (int e = tid; e < NPAD * 16; e += 256) {
            int n = e >> 4, kk = (e & 15) * 2;
            *(uint32_t*)&Ws[n * XS_STRIDE + kk] =
                *(const uint32_t*)(g_W1t + (size_t)n * DIM + c0 + kk);
        }
        __syncthreads();
        #pragma unroll
        for (int ks = 0; ks < 2; ++ks) {
            int kb = ks * 16 + 2 * l4;
            uint32_t a[4][4];
            #pragma unroll
            for (int mt = 0; mt < 4; ++mt) {
                int r = wm * 64 + mt * 16 + q;
                a[mt][0] = lds_u32(Xs, r * XS_STRIDE + kb);
                a[mt][1] = lds_u32(Xs, (r + 8) * XS_STRIDE + kb);
                a[mt][2] = lds_u32(Xs, r * XS_STRIDE + kb + 8);
                a[mt][3] = lds_u32(Xs, (r + 8) * XS_STRIDE + kb + 8);
            }
            #pragma unroll
            for (int nt = 0; nt < 8; ++nt) {
                int n = wn * 64 + nt * 8 + q;
                uint32_t bb[2];
                bb[0] = lds_u32(Ws, n * XS_STRIDE + kb);
                bb[1] = lds_u32(Ws, n * XS_STRIDE + kb + 8);
                #pragma unroll
                for (int mt = 0; mt < 4; ++mt)
                    mma16816(acc[mt][nt], a[mt], bb);
            }
        }
        __syncthreads();
    }

    // epilogue: + Ai + Bj + b1, relu, bf16 store
    #pragma unroll
    for (int mt = 0; mt < 4; ++mt) {
        #pragma unroll
        for (int half = 0; half < 2; ++half) {
            int r = wm * 64 + mt * 16 + q + 8 * half;
            int i = sII[r], j = sJJ[r];
            const float* Ai = g_AB + (size_t)(b * NSEL + i) * (2 * HID);
            const float* Bj = g_AB + (size_t)(b * NSEL + j) * (2 * HID) + HID;
            __nv_bfloat16* H = g_H1 + ((size_t)b * NPAIR + p0 + r) * K2PAD;
            #pragma unroll
            for (int nt = 0; nt < 8; ++nt) {
                int col = wn * 64 + nt * 8 + 2 * l4;
                if (col < HID) {
                    float2 ai = *(const float2*)(Ai + col);
                    float2 bj = *(const float2*)(Bj + col);
                    float v0 = acc[mt][nt][half * 2 + 0] + ai.x + bj.x + b1s[col];
                    float v1 = acc[mt][nt][half * 2 + 1] + ai.y + bj.y + b1s[col + 1];
                    __nv_bfloat162 o = __floats2bfloat162_rn(fmaxf(v0, 0.f), fmaxf(v1, 0.f));
                    *(uint32_t*)(H + col) = *(uint32_t*)&o;
                }
            }
        }
    }
}

// ================= layer 2 + scoring: mma.sync bf16 GEMM =================
__global__ __launch_bounds__(256)
void k_l2(const float* __restrict__ b2, const float* __restrict__ W3,
          const float* __restrict__ b3) {
    __shared__ __nv_bfloat16 Xs[MTILE * XS_STRIDE];
    __shared__ __nv_bfloat16 Ws[NPAD  * XS_STRIDE];
    __shared__ float b2s[HID], W3s[HID];
    __shared__ float sred[MTILE][4];

    int tid = threadIdx.x;
    int b = blockIdx.y;
    int p0 = blockIdx.x * MTILE;
    if (tid < HID) { b2s[tid] = b2[tid]; W3s[tid] = W3[tid]; }
    __syncthreads();

    int wid = tid / 32, lane = tid % 32;
    int wm = wid & 1, wn = wid >> 1;
    int q = lane >> 2, l4 = lane & 3;
    const __nv_bfloat16* Hbase = g_H1 + ((size_t)b * NPAIR + p0) * K2PAD;

    float acc[4][8][4];
    #pragma unroll
    for (int mt = 0; mt < 4; ++mt)
        #pragma unroll
        for (int nt = 0; nt < 8; ++nt)
            #pragma unroll
            for (int v = 0; v < 4; ++v) acc[mt][nt][v] = 0.f;

    for (int c = 0; c < K2PAD / 32; ++c) {
        int c0 = c * 32;
        for (int e = tid; e < MTILE * 16; e += 256) {
            int r = e >> 4, kk = (e & 15) * 2;
            *(uint32_t*)&Xs[r * XS_STRIDE + kk] =
                *(const uint32_t*)(Hbase + (size_t)r * K2PAD + c0 + kk);
        }
        for (int e = tid; e < NPAD * 16; e += 256) {
            int n = e >> 4, kk = (e & 15) * 2;
            *(uint32_t*)&Ws[n * XS_STRIDE + kk] =
                *(const uint32_t*)(g_W2t + (size_t)n * K2PAD + c0 + kk);
        }
        __syncthreads();
        #pragma unroll
        for (int ks = 0; ks < 2; ++ks) {
            int kb = ks * 16 + 2 * l4;
            uint32_t a[4][4];
            #pragma unroll
            for (int mt = 0; mt < 4; ++mt) {
                int r = wm * 64 + mt * 16 + q;
                a[mt][0] = lds_u32(Xs, r * XS_STRIDE + kb);
                a[mt][1] = lds_u32(Xs, (r + 8) * XS_STRIDE + kb);
                a[mt][2] = lds_u32(Xs, r * XS_STRIDE + kb + 8);
                a[mt][3] = lds_u32(Xs, (r + 8) * XS_STRIDE + kb + 8);
            }
            #pragma unroll
            for (int nt = 0; nt < 8; ++nt) {
                int n = wn * 64 + nt * 8 + q;
                uint32_t bb[2];
                bb[0] = lds_u32(Ws, n * XS_STRIDE + kb);
                bb[1] = lds_u32(Ws, n * XS_STRIDE + kb + 8);
                #pragma unroll
                for (int mt = 0; mt < 4; ++mt)
                    mma16816(acc[mt][nt], a[mt], bb);
            }
        }
        __syncthreads();
    }

    // epilogue: relu(acc + b2) . W3, reduce, scatter to g_S
    #pragma unroll
    for (int mt = 0; mt < 4; ++mt) {
        #pragma unroll
        for (int half = 0; half < 2; ++half) {
            float sp = 0.f;
            #pragma unroll
            for (int nt = 0; nt < 8; ++nt) {
                int col = wn * 64 + nt * 8 + 2 * l4;
                if (col < HID) {
                    float h0 = fmaxf(acc[mt][nt][half * 2 + 0] + b2s[col], 0.f);
                    float h1 = fmaxf(acc[mt][nt][half * 2 + 1] + b2s[col + 1], 0.f);
                    sp = fmaf(h0, W3s[col], sp);
                    sp = fmaf(h1, W3s[col + 1], sp);
                }
            }
            sp += __shfl_xor_sync(0xFFFFFFFFu, sp, 1);
            sp += __shfl_xor_sync(0xFFFFFFFFu, sp, 2);
            if (l4 == 0) {
                int r = wm * 64 + mt * 16 + q + 8 * half;
                sred[r][wn] = sp;
            }
        }
    }
    __syncthreads();
    if (tid < MTILE) {
        float s = sred[tid][0] + sred[tid][1] + sred[tid][2] + sred[tid][3] + b3[0];
        int p = p0 + tid;
        int i = g_II[p], j = g_JJ[p];
        g_S[((size_t)b * NSEL + i) * NSEL + j] = s;
    }
}

// ---------------- row softmax + fill ----------------
__global__ void k_soft(float* __restrict__ out) {
    int bn = blockIdx.x;
    int i = bn % NSEL;
    const float* Srow = g_S + (size_t)bn * NSEL;
    float* orow = out + (size_t)bn * NSEL;
    __shared__ float red[256];
    int tid = threadIdx.x;

    float mx = -1e30f;
    for (int j = tid; j <= i; j += 256) {
        float l = (j == i) ? 0.f : Srow[j];
        mx = fmaxf(mx, l);
    }
    red[tid] = mx; __syncthreads();
    for (int s = 128; s > 0; s >>= 1) {
        if (tid < s) red[tid] = fmaxf(red[tid], red[tid + s]);
        __syncthreads();
    }
    mx = red[0]; __syncthreads();

    float sum = 0.f;
    for (int j = tid; j <= i; j += 256) {
        float l = (j == i) ? 0.f : Srow[j];
        sum += __expf(l - mx);
    }
    red[tid] = sum; __syncthreads();
    for (int s = 128; s > 0; s >>= 1) {
        if (tid < s) red[tid] += red[tid + s];
        __syncthreads();
    }
    sum = red[0];
    float inv = 1.0f / sum;

    for (int j = tid; j < NSEL; j += 256) {
        if (j <= i) {
            float l = (j == i) ? 0.f : Srow[j];
            orow[j] = __expf(l - mx) * inv;
        } else {
            orow[j] = -1000.0f;
        }
    }
}

// ---------------- launch ----------------
extern "C" void kernel_launch(void* const* d_in, const int* in_sizes, int n_in,
                              void* d_out, int out_size) {
    const float* emb = (const float*)d_in[0];
    const int*   idx = (const int*)  d_in[1];
    const float* W1  = (const float*)d_in[2];
    const float* b1  = (const float*)d_in[3];
    const float* W2  = (const float*)d_in[4];
    const float* b2  = (const float*)d_in[5];
    const float* W3  = (const float*)d_in[6];
    const float* b3  = (const float*)d_in[7];
    float* out = (float*)d_out;

    k_pairs<<<(NPAIR + 255) / 256, 256>>>();
    k_gather<<<BATCH * NSEL, 192>>>(emb, idx);
    k_w1t<<<(NPAD * DIM + 255) / 256, 256>>>(W1);
    k_w2t<<<(NPAD * K2PAD + 255) / 256, 256>>>(W2);
    k_ab<<<dim3(16, 7), 256>>>(W1);
    k_l1<<<dim3(NT1, BATCH), 256>>>(b1);
    k_l2<<<dim3(NT1, BATCH), 256>>>(b2, W3, b3);
    k_soft<<<BATCH * NSEL, 256>>>(out);
}

// round 6
// speedup vs baseline: 5.4066x; 1.9117x over previous
#include <cuda_runtime.h>
#include <cuda_bf16.h>
#include <math.h>
#include <stdint.h>

#define BATCH 4
#define TLEN  4096
#define DIM   768
#define NSEL  256
#define HID   200
#define NPAIR 32640          // NSEL*(NSEL-1)/2
#define MTILE 128            // pairs per CTA
#define NPAD  256            // padded hidden (cols 200..255 zero-weight)
#define NT1   255            // NPAIR / MTILE
#define K2PAD 256            // padded K for layer 2
#define XS_STRIDE 40         // bf16 elems per smem row (80B)
#define HS_STRIDE 264        // bf16 elems per Hs row (528B)
#define L1C   (DIM / 32)     // 24 chunks
#define L2C   (K2PAD / 32)   // 8 chunks

// dynamic smem layout (bytes)
#define XS0_OFF 0
#define XS1_OFF (MTILE * XS_STRIDE * 2)                 // 10240
#define WS0_OFF (2 * MTILE * XS_STRIDE * 2)             // 20480
#define WS1_OFF (WS0_OFF + NPAD * XS_STRIDE * 2)        // 40960
#define HS_OFF  (WS1_OFF + NPAD * XS_STRIDE * 2)        // 61440
#define DYN_BYTES (HS_OFF + MTILE * HS_STRIDE * 2)      // 129024

// ---------------- device scratch ----------------
__device__ float          g_E  [BATCH * NSEL * DIM];
__device__ float          g_AB [BATCH * NSEL * 2 * HID];
__device__ __nv_bfloat16  g_W1t[NPAD * DIM];            // [h][d], rows>=200 zero
__device__ __nv_bfloat16  g_W2t[NPAD * K2PAD];          // [h][k], pads zero
__device__ float          g_S  [BATCH * NSEL * NSEL];
__device__ int            g_II [NPAIR];
__device__ int            g_JJ [NPAIR];

// ---------------- helpers ----------------
__device__ __forceinline__ void mma16816(float* c, const uint32_t* a, const uint32_t* b) {
    asm volatile(
        "mma.sync.aligned.m16n8k16.row.col.f32.bf16.bf16.f32 "
        "{%0,%1,%2,%3}, {%4,%5,%6,%7}, {%8,%9}, {%0,%1,%2,%3};"
        : "+f"(c[0]), "+f"(c[1]), "+f"(c[2]), "+f"(c[3])
        : "r"(a[0]), "r"(a[1]), "r"(a[2]), "r"(a[3]), "r"(b[0]), "r"(b[1]));
}
__device__ __forceinline__ uint32_t lds_u32(const __nv_bfloat16* base, int elem_off) {
    return *(const uint32_t*)((const char*)base + elem_off * 2);
}
__device__ __forceinline__ void cpasync16(uint32_t smem_addr, const void* gsrc) {
    asm volatile("cp.async.cg.shared.global [%0], [%1], 16;"
                 :: "r"(smem_addr), "l"(gsrc) : "memory");
}
__device__ __forceinline__ void cpasync_commit() {
    asm volatile("cp.async.commit_group;" ::: "memory");
}
__device__ __forceinline__ void cpasync_wait0() {
    asm volatile("cp.async.wait_group 0;" ::: "memory");
}

// ---------------- pair index table ----------------
__global__ void k_pairs() {
    int p = blockIdx.x * blockDim.x + threadIdx.x;
    if (p >= NPAIR) return;
    int i = (int)((1.0f + sqrtf(1.0f + 8.0f * (float)p)) * 0.5f);
    while (i > 1 && i * (i - 1) / 2 > p) --i;
    while ((i + 1) * i / 2 <= p) ++i;
    g_II[p] = i;
    g_JJ[p] = p - i * (i - 1) / 2;
}

// ---------------- gather ----------------
__global__ void k_gather(const float* __restrict__ emb, const int* __restrict__ idx) {
    int bn = blockIdx.x;
    int b = bn / NSEL, n = bn % NSEL;
    int t = idx[b * NSEL + n];
    const float4* src = (const float4*)(emb + ((size_t)b * TLEN + t) * DIM);
    float4* dst = (float4*)(g_E + (size_t)bn * DIM);
    for (int d = threadIdx.x; d < DIM / 4; d += blockDim.x) dst[d] = src[d];
}

// ---------------- weight transposes (bf16, K-major, zero-padded) ----------------
__global__ void k_w1t(const float* __restrict__ W1) {
    int e = blockIdx.x * blockDim.x + threadIdx.x;
    if (e >= NPAD * DIM) return;
    int h = e / DIM, d = e % DIM;
    float v = (h < HID) ? W1[(size_t)(2 * DIM + d) * HID + h] : 0.f;
    g_W1t[e] = __float2bfloat16(v);
}
__global__ void k_w2t(const float* __restrict__ W2) {
    int e = blockIdx.x * blockDim.x + threadIdx.x;
    if (e >= NPAD * K2PAD) return;
    int h = e / K2PAD, k = e % K2PAD;
    float v = (h < HID && k < HID) ? W2[(size_t)k * HID + h] : 0.f;
    g_W2t[e] = __float2bfloat16(v);
}

// ---------------- exact A/B partials (fp32 SIMT, small) ----------------
__global__ void k_ab(const float* __restrict__ W1) {
    __shared__ __align__(16) float As[16][64 + 4];
    __shared__ __align__(16) float Bs[16][64 + 4];
    int bm = blockIdx.x * 64, bn = blockIdx.y * 64;
    int tx = threadIdx.x % 16, ty = threadIdx.x / 16;
    float acc[4][4] = {};
    for (int k0 = 0; k0 < DIM; k0 += 16) {
        for (int t = threadIdx.x; t < 1024; t += 256) {
            int k = t % 16, m = t / 16;
            As[k][m] = g_E[(size_t)(bm + m) * DIM + k0 + k];
        }
        for (int t = threadIdx.x; t < 1024; t += 256) {
            int n = t % 64, k = t / 64;
            int c = bn + n;
            float v = 0.f;
            if (c < 2 * HID) {
                int half = c / HID, h = c - half * HID;
                v = W1[(size_t)(half * DIM + k0 + k) * HID + h];
            }
            Bs[k][n] = v;
        }
        __syncthreads();
        #pragma unroll
        for (int k = 0; k < 16; ++k) {
            float a[4], bb[4];
            #pragma unroll
            for (int u = 0; u < 4; ++u) a[u] = As[k][ty * 4 + u];
            #pragma unroll
            for (int v = 0; v < 4; ++v) bb[v] = Bs[k][tx * 4 + v];
            #pragma unroll
            for (int u = 0; u < 4; ++u)
                #pragma unroll
                for (int v = 0; v < 4; ++v)
                    acc[u][v] = fmaf(a[u], bb[v], acc[u][v]);
        }
        __syncthreads();
    }
    #pragma unroll
    for (int u = 0; u < 4; ++u)
        #pragma unroll
        for (int v = 0; v < 4; ++v) {
            int c = bn + tx * 4 + v;
            if (c < 2 * HID)
                g_AB[(size_t)(bm + ty * 4 + u) * (2 * HID) + c] = acc[u][v];
        }
}

// ================= fused MLP: layer1 GEMM -> Hs smem -> layer2 GEMM -> score =================
// CTA: 128 pairs. 8 warps, warp tile 64x64 over NPAD=256.
__global__ __launch_bounds__(256)
void k_fused(const float* __restrict__ b1, const float* __restrict__ b2,
             const float* __restrict__ W3, const float* __restrict__ b3) {
    extern __shared__ __align__(16) char dynsm[];
    __nv_bfloat16* XsBuf[2] = { (__nv_bfloat16*)(dynsm + XS0_OFF),
                                (__nv_bfloat16*)(dynsm + XS1_OFF) };
    __nv_bfloat16* WsBuf[2] = { (__nv_bfloat16*)(dynsm + WS0_OFF),
                                (__nv_bfloat16*)(dynsm + WS1_OFF) };
    __nv_bfloat16* Hs = (__nv_bfloat16*)(dynsm + HS_OFF);
    uint32_t ws_base[2] = { (uint32_t)__cvta_generic_to_shared(WsBuf[0]),
                            (uint32_t)__cvta_generic_to_shared(WsBuf[1]) };

    __shared__ int sII[MTILE], sJJ[MTILE];
    __shared__ float b1s[HID], b2s[HID], W3s[HID];
    __shared__ float sred[MTILE][4];

    int tid = threadIdx.x;
    int b = blockIdx.y;
    int p0 = blockIdx.x * MTILE;
    if (tid < MTILE) { sII[tid] = g_II[p0 + tid]; sJJ[tid] = g_JJ[p0 + tid]; }
    if (tid < HID) { b1s[tid] = b1[tid]; b2s[tid] = b2[tid]; W3s[tid] = W3[tid]; }

    const float* Eb = g_E + (size_t)b * NSEL * DIM;
    int wid = tid / 32, lane = tid % 32;
    int wm = wid & 1, wn = wid >> 1;
    int q = lane >> 2, l4 = lane & 3;

    // precompute this thread's X-fill coordinates (8 u32 per thread)
    int xr[8], xk[8];
    #pragma unroll
    for (int u = 0; u < 8; ++u) {
        int e = tid + u * 256;
        xr[u] = e >> 4;
        xk[u] = (e & 15) * 2;
    }
    __syncthreads();

    float acc[4][8][4];
    #pragma unroll
    for (int mt = 0; mt < 4; ++mt)
        #pragma unroll
        for (int nt = 0; nt < 8; ++nt)
            #pragma unroll
            for (int v = 0; v < 4; ++v) acc[mt][nt][v] = 0.f;

    // ---------------- layer-1 mainloop (pipelined, double-buffered) ----------------
    // prologue: fill chunk 0
    {
        #pragma unroll
        for (int u = 0; u < 8; ++u) {
            const float2 xi = *(const float2*)(Eb + (size_t)sII[xr[u]] * DIM + xk[u]);
            const float2 xj = *(const float2*)(Eb + (size_t)sJJ[xr[u]] * DIM + xk[u]);
            __nv_bfloat162 v = __floats2bfloat162_rn(xi.x * xj.x, xi.y * xj.y);
            *(uint32_t*)&XsBuf[0][xr[u] * XS_STRIDE + xk[u]] = *(uint32_t*)&v;
        }
        #pragma unroll
        for (int u = 0; u < 4; ++u) {
            int e = tid + u * 256;
            int n = e >> 2, seg = e & 3;
            cpasync16(ws_base[0] + n * (XS_STRIDE * 2) + seg * 16,
                      g_W1t + (size_t)n * DIM + seg * 8);
        }
        cpasync_commit();
        cpasync_wait0();
        __syncthreads();
    }

    for (int c = 0; c < L1C; ++c) {
        const __nv_bfloat16* Xs = XsBuf[c & 1];
        const __nv_bfloat16* Ws = WsBuf[c & 1];
        int nb = (c + 1) & 1;
        bool more = (c + 1 < L1C);
        int c0n = (c + 1) * 32;

        // 1. kick off W(c+1) cp.async
        if (more) {
            #pragma unroll
            for (int u = 0; u < 4; ++u) {
                int e = tid + u * 256;
                int n = e >> 2, seg = e & 3;
                cpasync16(ws_base[nb] + n * (XS_STRIDE * 2) + seg * 16,
                          g_W1t + (size_t)n * DIM + c0n + seg * 8);
            }
            cpasync_commit();
        }
        // 2. prefetch E(c+1)
        float2 pxi[8], pxj[8];
        if (more) {
            #pragma unroll
            for (int u = 0; u < 8; ++u) {
                pxi[u] = *(const float2*)(Eb + (size_t)sII[xr[u]] * DIM + c0n + xk[u]);
                pxj[u] = *(const float2*)(Eb + (size_t)sJJ[xr[u]] * DIM + c0n + xk[u]);
            }
        }
        // 3. MMA(c)
        #pragma unroll
        for (int ks = 0; ks < 2; ++ks) {
            int kb = ks * 16 + 2 * l4;
            uint32_t a[4][4];
            #pragma unroll
            for (int mt = 0; mt < 4; ++mt) {
                int r = wm * 64 + mt * 16 + q;
                a[mt][0] = lds_u32(Xs, r * XS_STRIDE + kb);
                a[mt][1] = lds_u32(Xs, (r + 8) * XS_STRIDE + kb);
                a[mt][2] = lds_u32(Xs, r * XS_STRIDE + kb + 8);
                a[mt][3] = lds_u32(Xs, (r + 8) * XS_STRIDE + kb + 8);
            }
            #pragma unroll
            for (int nt = 0; nt < 8; ++nt) {
                int n = wn * 64 + nt * 8 + q;
                uint32_t bb[2];
                bb[0] = lds_u32(Ws, n * XS_STRIDE + kb);
                bb[1] = lds_u32(Ws, n * XS_STRIDE + kb + 8);
                #pragma unroll
                for (int mt = 0; mt < 4; ++mt)
                    mma16816(acc[mt][nt], a[mt], bb);
            }
        }
        // 4. convert + store X(c+1)
        if (more) {
            #pragma unroll
            for (int u = 0; u < 8; ++u) {
                __nv_bfloat162 v = __floats2bfloat162_rn(pxi[u].x * pxj[u].x,
                                                         pxi[u].y * pxj[u].y);
                *(uint32_t*)&XsBuf[nb][xr[u] * XS_STRIDE + xk[u]] = *(uint32_t*)&v;
            }
        }
        cpasync_wait0();
        __syncthreads();
    }

    // ---------------- layer-1 epilogue: acc + Ai + Bj + b1, relu -> Hs (bf16) ----------------
    #pragma unroll
    for (int mt = 0; mt < 4; ++mt) {
        #pragma unroll
        for (int half = 0; half < 2; ++half) {
            int r = wm * 64 + mt * 16 + q + 8 * half;
            int i = sII[r], j = sJJ[r];
            const float* Ai = g_AB + (size_t)(b * NSEL + i) * (2 * HID);
            const float* Bj = g_AB + (size_t)(b * NSEL + j) * (2 * HID) + HID;
            #pragma unroll
            for (int nt = 0; nt < 8; ++nt) {
                int col = wn * 64 + nt * 8 + 2 * l4;
                if (col < HID) {
                    float2 ai = *(const float2*)(Ai + col);
                    float2 bj = *(const float2*)(Bj + col);
                    float v0 = acc[mt][nt][half * 2 + 0] + ai.x + bj.x + b1s[col];
                    float v1 = acc[mt][nt][half * 2 + 1] + ai.y + bj.y + b1s[col + 1];
                    __nv_bfloat162 o = __floats2bfloat162_rn(fmaxf(v0, 0.f), fmaxf(v1, 0.f));
                    *(uint32_t*)&Hs[r * HS_STRIDE + col] = *(uint32_t*)&o;
                }
            }
        }
    }
    // zero pad cols [200,256) of Hs
    for (int e = tid; e < MTILE * 28; e += 256) {
        int r = e / 28, cc = HID + (e % 28) * 2;
        *(uint32_t*)&Hs[r * HS_STRIDE + cc] = 0u;
    }
    __syncthreads();

    // re-init acc for layer 2
    #pragma unroll
    for (int mt = 0; mt < 4; ++mt)
        #pragma unroll
        for (int nt = 0; nt < 8; ++nt)
            #pragma unroll
            for (int v = 0; v < 4; ++v) acc[mt][nt][v] = 0.f;

    // ---------------- layer-2 mainloop: A from Hs, W2 double-buffered ----------------
    {
        #pragma unroll
        for (int u = 0; u < 4; ++u) {
            int e = tid + u * 256;
            int n = e >> 2, seg = e & 3;
            cpasync16(ws_base[0] + n * (XS_STRIDE * 2) + seg * 16,
                      g_W2t + (size_t)n * K2PAD + seg * 8);
        }
        cpasync_commit();
        cpasync_wait0();
        __syncthreads();
    }
    for (int c = 0; c < L2C; ++c) {
        const __nv_bfloat16* Ws = WsBuf[c & 1];
        int nb = (c + 1) & 1;
        if (c + 1 < L2C) {
            int c0n = (c + 1) * 32;
            #pragma unroll
            for (int u = 0; u < 4; ++u) {
                int e = tid + u * 256;
                int n = e >> 2, seg = e & 3;
                cpasync16(ws_base[nb] + n * (XS_STRIDE * 2) + seg * 16,
                          g_W2t + (size_t)n * K2PAD + c0n + seg * 8);
            }
            cpasync_commit();
        }
        int c0 = c * 32;
        #pragma unroll
        for (int ks = 0; ks < 2; ++ks) {
            int kb = ks * 16 + 2 * l4;
            uint32_t a[4][4];
            #pragma unroll
            for (int mt = 0; mt < 4; ++mt) {
                int r = wm * 64 + mt * 16 + q;
                a[mt][0] = lds_u32(Hs, r * HS_STRIDE + c0 + kb);
                a[mt][1] = lds_u32(Hs, (r + 8) * HS_STRIDE + c0 + kb);
                a[mt][2] = lds_u32(Hs, r * HS_STRIDE + c0 + kb + 8);
                a[mt][3] = lds_u32(Hs, (r + 8) * HS_STRIDE + c0 + kb + 8);
            }
            #pragma unroll
            for (int nt = 0; nt < 8; ++nt) {
                int n = wn * 64 + nt * 8 + q;
                uint32_t bb[2];
                bb[0] = lds_u32(Ws, n * XS_STRIDE + kb);
                bb[1] = lds_u32(Ws, n * XS_STRIDE + kb + 8);
                #pragma unroll
                for (int mt = 0; mt < 4; ++mt)
                    mma16816(acc[mt][nt], a[mt], bb);
            }
        }
        cpasync_wait0();
        __syncthreads();
    }

    // ---------------- scoring epilogue ----------------
    #pragma unroll
    for (int mt = 0; mt < 4; ++mt) {
        #pragma unroll
        for (int half = 0; half < 2; ++half) {
            float sp = 0.f;
            #pragma unroll
            for (int nt = 0; nt < 8; ++nt) {
                int col = wn * 64 + nt * 8 + 2 * l4;
                if (col < HID) {
                    float h0 = fmaxf(acc[mt][nt][half * 2 + 0] + b2s[col], 0.f);
                    float h1 = fmaxf(acc[mt][nt][half * 2 + 1] + b2s[col + 1], 0.f);
                    sp = fmaf(h0, W3s[col], sp);
                    sp = fmaf(h1, W3s[col + 1], sp);
                }
            }
            sp += __shfl_xor_sync(0xFFFFFFFFu, sp, 1);
            sp += __shfl_xor_sync(0xFFFFFFFFu, sp, 2);
            if (l4 == 0) {
                int r = wm * 64 + mt * 16 + q + 8 * half;
                sred[r][wn] = sp;
            }
        }
    }
    __syncthreads();
    if (tid < MTILE) {
        float s = sred[tid][0] + sred[tid][1] + sred[tid][2] + sred[tid][3] + b3[0];
        int i = sII[tid], j = sJJ[tid];
        g_S[((size_t)b * NSEL + i) * NSEL + j] = s;
    }
}

// ---------------- row softmax + fill ----------------
__global__ void k_soft(float* __restrict__ out) {
    int bn = blockIdx.x;
    int i = bn % NSEL;
    const float* Srow = g_S + (size_t)bn * NSEL;
    float* orow = out + (size_t)bn * NSEL;
    __shared__ float red[256];
    int tid = threadIdx.x;

    float mx = -1e30f;
    for (int j = tid; j <= i; j += 256) {
        float l = (j == i) ? 0.f : Srow[j];
        mx = fmaxf(mx, l);
    }
    red[tid] = mx; __syncthreads();
    for (int s = 128; s > 0; s >>= 1) {
        if (tid < s) red[tid] = fmaxf(red[tid], red[tid + s]);
        __syncthreads();
    }
    mx = red[0]; __syncthreads();

    float sum = 0.f;
    for (int j = tid; j <= i; j += 256) {
        float l = (j == i) ? 0.f : Srow[j];
        sum += __expf(l - mx);
    }
    red[tid] = sum; __syncthreads();
    for (int s = 128; s > 0; s >>= 1) {
        if (tid < s) red[tid] += red[tid + s];
        __syncthreads();
    }
    sum = red[0];
    float inv = 1.0f / sum;

    for (int j = tid; j < NSEL; j += 256) {
        if (j <= i) {
            float l = (j == i) ? 0.f : Srow[j];
            orow[j] = __expf(l - mx) * inv;
        } else {
            orow[j] = -1000.0f;
        }
    }
}

// ---------------- launch ----------------
extern "C" void kernel_launch(void* const* d_in, const int* in_sizes, int n_in,
                              void* d_out, int out_size) {
    const float* emb = (const float*)d_in[0];
    const int*   idx = (const int*)  d_in[1];
    const float* W1  = (const float*)d_in[2];
    const float* b1  = (const float*)d_in[3];
    const float* W2  = (const float*)d_in[4];
    const float* b2  = (const float*)d_in[5];
    const float* W3  = (const float*)d_in[6];
    const float* b3  = (const float*)d_in[7];
    float* out = (float*)d_out;

    static int configured = 0;
    if (!configured) {
        cudaFuncSetAttribute(k_fused, cudaFuncAttributeMaxDynamicSharedMemorySize,
                             DYN_BYTES);
        configured = 1;
    }

    k_pairs<<<(NPAIR + 255) / 256, 256>>>();
    k_gather<<<BATCH * NSEL, 192>>>(emb, idx);
    k_w1t<<<(NPAD * DIM + 255) / 256, 256>>>(W1);
    k_w2t<<<(NPAD * K2PAD + 255) / 256, 256>>>(W2);
    k_ab<<<dim3(16, 7), 256>>>(W1);
    k_fused<<<dim3(NT1, BATCH), 256, DYN_BYTES>>>(b1, b2, W3, b3);
    k_soft<<<BATCH * NSEL, 256>>>(out);
}

// round 7
// speedup vs baseline: 5.9033x; 1.0919x over previous
#include <cuda_runtime.h>
#include <cuda_bf16.h>
#include <math.h>
#include <stdint.h>

#define BATCH 4
#define TLEN  4096
#define DIM   768
#define NSEL  256
#define HID   200
#define NPAIR 32640          // NSEL*(NSEL-1)/2
#define MTILE 128            // pairs per CTA
#define NT1   255            // NPAIR / MTILE
#define K2PAD 224            // padded K for layer 2 (7 chunks of 32)
#define XS_STRIDE 40         // bf16 elems per smem row (80B)
#define HS_STRIDE 232        // bf16 elems per Hs row (464B)
#define L1C   (DIM / 32)     // 24 chunks
#define L2C   (K2PAD / 32)   // 7 chunks
#define NTILES 25            // 200/8 n-tiles

// dynamic smem layout (bytes)
#define XS0_OFF 0
#define XS1_OFF (MTILE * XS_STRIDE * 2)                 // 10240
#define WS0_OFF (2 * MTILE * XS_STRIDE * 2)             // 20480
#define WS1_OFF (WS0_OFF + HID * XS_STRIDE * 2)         // 36480
#define HS_OFF  (WS1_OFF + HID * XS_STRIDE * 2)         // 52480
#define DYN_BYTES (HS_OFF + MTILE * HS_STRIDE * 2)      // 111872

// ---------------- device scratch ----------------
__device__ float          g_E  [BATCH * NSEL * DIM];
__device__ float          g_AB [BATCH * NSEL * 2 * HID];
__device__ __nv_bfloat16  g_W1t[HID * DIM];             // [h][d]
__device__ __nv_bfloat16  g_W2t[HID * K2PAD];           // [h][k], k>=200 zero
__device__ float          g_S  [BATCH * NSEL * NSEL];
__device__ int            g_II [NPAIR];
__device__ int            g_JJ [NPAIR];

// ---------------- helpers ----------------
__device__ __forceinline__ void mma16816(float* c, const uint32_t* a, const uint32_t* b) {
    asm volatile(
        "mma.sync.aligned.m16n8k16.row.col.f32.bf16.bf16.f32 "
        "{%0,%1,%2,%3}, {%4,%5,%6,%7}, {%8,%9}, {%0,%1,%2,%3};"
        : "+f"(c[0]), "+f"(c[1]), "+f"(c[2]), "+f"(c[3])
        : "r"(a[0]), "r"(a[1]), "r"(a[2]), "r"(a[3]), "r"(b[0]), "r"(b[1]));
}
__device__ __forceinline__ void ldsm_x4(uint32_t* r, uint32_t addr) {
    asm volatile("ldmatrix.sync.aligned.m8n8.x4.shared.b16 {%0,%1,%2,%3}, [%4];"
                 : "=r"(r[0]), "=r"(r[1]), "=r"(r[2]), "=r"(r[3]) : "r"(addr));
}
__device__ __forceinline__ void ldsm_x2(uint32_t* r, uint32_t addr) {
    asm volatile("ldmatrix.sync.aligned.m8n8.x2.shared.b16 {%0,%1}, [%2];"
                 : "=r"(r[0]), "=r"(r[1]) : "r"(addr));
}
__device__ __forceinline__ void cpasync16(uint32_t smem_addr, const void* gsrc) {
    asm volatile("cp.async.cg.shared.global [%0], [%1], 16;"
                 :: "r"(smem_addr), "l"(gsrc) : "memory");
}
__device__ __forceinline__ void cpasync_commit() {
    asm volatile("cp.async.commit_group;" ::: "memory");
}
__device__ __forceinline__ void cpasync_wait0() {
    asm volatile("cp.async.wait_group 0;" ::: "memory");
}

// ---------------- fused prep: pairs + gather + W1t + W2t ----------------
#define PREP_PAIRS 128
#define PREP_GATH  (BATCH * NSEL)                       // 1024
#define PREP_W1    ((HID * DIM + 255) / 256)            // 600
#define PREP_W2    ((HID * K2PAD + 255) / 256)          // 175
#define PREP_BLKS  (PREP_PAIRS + PREP_GATH + PREP_W1 + PREP_W2)

__global__ void k_prep(const float* __restrict__ emb, const int* __restrict__ idx,
                       const float* __restrict__ W1, const float* __restrict__ W2) {
    int blk = blockIdx.x;
    int tid = threadIdx.x;
    if (blk < PREP_PAIRS) {
        int p = blk * 256 + tid;
        if (p < NPAIR) {
            int i = (int)((1.0f + sqrtf(1.0f + 8.0f * (float)p)) * 0.5f);
            while (i > 1 && i * (i - 1) / 2 > p) --i;
            while ((i + 1) * i / 2 <= p) ++i;
            g_II[p] = i;
            g_JJ[p] = p - i * (i - 1) / 2;
        }
        return;
    }
    blk -= PREP_PAIRS;
    if (blk < PREP_GATH) {
        int b = blk / NSEL, n = blk % NSEL;
        int t = idx[b * NSEL + n];
        const float4* src = (const float4*)(emb + ((size_t)b * TLEN + t) * DIM);
        float4* dst = (float4*)(g_E + (size_t)blk * DIM);
        if (tid < DIM / 4) dst[tid] = src[tid];
        return;
    }
    blk -= PREP_GATH;
    if (blk < PREP_W1) {
        int e = blk * 256 + tid;
        if (e < HID * DIM) {
            int h = e / DIM, d = e % DIM;
            g_W1t[e] = __float2bfloat16(W1[(size_t)(2 * DIM + d) * HID + h]);
        }
        return;
    }
    blk -= PREP_W1;
    {
        int e = blk * 256 + tid;
        if (e < HID * K2PAD) {
            int h = e / K2PAD, k = e % K2PAD;
            float v = (k < HID) ? W2[(size_t)k * HID + h] : 0.f;
            g_W2t[e] = __float2bfloat16(v);
        }
    }
}

// ---------------- exact A/B partials (fp32 SIMT, small) ----------------
__global__ void k_ab(const float* __restrict__ W1) {
    __shared__ __align__(16) float As[16][64 + 4];
    __shared__ __align__(16) float Bs[16][64 + 4];
    int bm = blockIdx.x * 64, bn = blockIdx.y * 64;
    int tx = threadIdx.x % 16, ty = threadIdx.x / 16;
    float acc[4][4] = {};
    for (int k0 = 0; k0 < DIM; k0 += 16) {
        for (int t = threadIdx.x; t < 1024; t += 256) {
            int k = t % 16, m = t / 16;
            As[k][m] = g_E[(size_t)(bm + m) * DIM + k0 + k];
        }
        for (int t = threadIdx.x; t < 1024; t += 256) {
            int n = t % 64, k = t / 64;
            int c = bn + n;
            float v = 0.f;
            if (c < 2 * HID) {
                int half = c / HID, h = c - half * HID;
                v = W1[(size_t)(half * DIM + k0 + k) * HID + h];
            }
            Bs[k][n] = v;
        }
        __syncthreads();
        #pragma unroll
        for (int k = 0; k < 16; ++k) {
            float a[4], bb[4];
            #pragma unroll
            for (int u = 0; u < 4; ++u) a[u] = As[k][ty * 4 + u];
            #pragma unroll
            for (int v = 0; v < 4; ++v) bb[v] = Bs[k][tx * 4 + v];
            #pragma unroll
            for (int u = 0; u < 4; ++u)
                #pragma unroll
                for (int v = 0; v < 4; ++v)
                    acc[u][v] = fmaf(a[u], bb[v], acc[u][v]);
        }
        __syncthreads();
    }
    #pragma unroll
    for (int u = 0; u < 4; ++u)
        #pragma unroll
        for (int v = 0; v < 4; ++v) {
            int c = bn + tx * 4 + v;
            if (c < 2 * HID)
                g_AB[(size_t)(bm + ty * 4 + u) * (2 * HID) + c] = acc[u][v];
        }
}

// ================= fused MLP =================
// CTA: 128 pairs. 8 warps (wm = wid&1 -> 64 rows, wn = wid>>1).
// N tiles: 25 tiles of 8 cols interleaved: warp wn owns nt_g = wn + 4t (t<7, nt_g<25).
__global__ __launch_bounds__(256)
void k_fused(const float* __restrict__ b1, const float* __restrict__ b2,
             const float* __restrict__ W3, const float* __restrict__ b3) {
    extern __shared__ __align__(16) char dynsm[];
    __nv_bfloat16* XsBuf[2] = { (__nv_bfloat16*)(dynsm + XS0_OFF),
                                (__nv_bfloat16*)(dynsm + XS1_OFF) };
    uint32_t dynbase = (uint32_t)__cvta_generic_to_shared(dynsm);
    uint32_t xs_base[2] = { dynbase + XS0_OFF, dynbase + XS1_OFF };
    uint32_t ws_base[2] = { dynbase + WS0_OFF, dynbase + WS1_OFF };
    uint32_t hs_base = dynbase + HS_OFF;
    __nv_bfloat16* Hs = (__nv_bfloat16*)(dynsm + HS_OFF);

    __shared__ int sII[MTILE], sJJ[MTILE];
    __shared__ float b1s[HID], b2s[HID], W3s[HID];
    __shared__ float sred[MTILE][4];

    int tid = threadIdx.x;
    int b = blockIdx.y;
    int p0 = blockIdx.x * MTILE;
    if (tid < MTILE) { sII[tid] = g_II[p0 + tid]; sJJ[tid] = g_JJ[p0 + tid]; }
    if (tid < HID) { b1s[tid] = b1[tid]; b2s[tid] = b2[tid]; W3s[tid] = W3[tid]; }

    const float* Eb = g_E + (size_t)b * NSEL * DIM;
    int wid = tid / 32, lane = tid % 32;
    int wm = wid & 1, wn = wid >> 1;
    int q = lane >> 2, l4 = lane & 3;

    // ldmatrix per-thread address components
    int rowA = wm * 64 + (lane & 15);          // + mt*16
    int colhA = (lane >> 4) * 8;               // elems
    int rowB = lane & 7;                       // + nt_g*8
    int colhB = ((lane >> 3) & 1) * 8;

    // X-fill coordinates (8 u32 per thread)
    int xr[8], xk[8];
    #pragma unroll
    for (int u = 0; u < 8; ++u) {
        int e = tid + u * 256;
        xr[u] = e >> 4;
        xk[u] = (e & 15) * 2;
    }
    __syncthreads();

    float acc[4][7][4];
    #pragma unroll
    for (int mt = 0; mt < 4; ++mt)
        #pragma unroll
        for (int t = 0; t < 7; ++t)
            #pragma unroll
            for (int v = 0; v < 4; ++v) acc[mt][t][v] = 0.f;

    // ---------------- layer-1 mainloop ----------------
    {
        #pragma unroll
        for (int u = 0; u < 8; ++u) {
            const float2 xi = *(const float2*)(Eb + (size_t)sII[xr[u]] * DIM + xk[u]);
            const float2 xj = *(const float2*)(Eb + (size_t)sJJ[xr[u]] * DIM + xk[u]);
            __nv_bfloat162 v = __floats2bfloat162_rn(xi.x * xj.x, xi.y * xj.y);
            *(uint32_t*)&XsBuf[0][xr[u] * XS_STRIDE + xk[u]] = *(uint32_t*)&v;
        }
        #pragma unroll
        for (int u = 0; u < 4; ++u) {
            int e = tid + u * 256;
            if (e < HID * 4) {
                int n = e >> 2, seg = e & 3;
                cpasync16(ws_base[0] + n * (XS_STRIDE * 2) + seg * 16,
                          g_W1t + (size_t)n * DIM + seg * 8);
            }
        }
        cpasync_commit();
        cpasync_wait0();
        __syncthreads();
    }

    for (int c = 0; c < L1C; ++c) {
        uint32_t xsb = xs_base[c & 1];
        uint32_t wsb = ws_base[c & 1];
        int nb = (c + 1) & 1;
        bool more = (c + 1 < L1C);
        int c0n = (c + 1) * 32;

        if (more) {
            #pragma unroll
            for (int u = 0; u < 4; ++u) {
                int e = tid + u * 256;
                if (e < HID * 4) {
                    int n = e >> 2, seg = e & 3;
                    cpasync16(ws_base[nb] + n * (XS_STRIDE * 2) + seg * 16,
                              g_W1t + (size_t)n * DIM + c0n + seg * 8);
                }
            }
            cpasync_commit();
        }
        float2 pxi[8], pxj[8];
        if (more) {
            #pragma unroll
            for (int u = 0; u < 8; ++u) {
                pxi[u] = *(const float2*)(Eb + (size_t)sII[xr[u]] * DIM + c0n + xk[u]);
                pxj[u] = *(const float2*)(Eb + (size_t)sJJ[xr[u]] * DIM + c0n + xk[u]);
            }
        }
        #pragma unroll
        for (int ks = 0; ks < 2; ++ks) {
            int kb = ks * 16;
            uint32_t a[4][4];
            #pragma unroll
            for (int mt = 0; mt < 4; ++mt)
                ldsm_x4(a[mt], xsb + ((rowA + mt * 16) * XS_STRIDE + kb + colhA) * 2);
            #pragma unroll
            for (int t = 0; t < 7; ++t) {
                int nt_g = wn + 4 * t;
                if (nt_g < NTILES) {
                    uint32_t bb[2];
                    ldsm_x2(bb, wsb + ((nt_g * 8 + rowB) * XS_STRIDE + kb + colhB) * 2);
                    #pragma unroll
                    for (int mt = 0; mt < 4; ++mt)
                        mma16816(acc[mt][t], a[mt], bb);
                }
            }
        }
        if (more) {
            #pragma unroll
            for (int u = 0; u < 8; ++u) {
                __nv_bfloat162 v = __floats2bfloat162_rn(pxi[u].x * pxj[u].x,
                                                         pxi[u].y * pxj[u].y);
                *(uint32_t*)&XsBuf[nb][xr[u] * XS_STRIDE + xk[u]] = *(uint32_t*)&v;
            }
        }
        cpasync_wait0();
        __syncthreads();
    }

    // ---------------- layer-1 epilogue -> Hs ----------------
    #pragma unroll
    for (int mt = 0; mt < 4; ++mt) {
        #pragma unroll
        for (int half = 0; half < 2; ++half) {
            int r = wm * 64 + mt * 16 + q + 8 * half;
            int i = sII[r], j = sJJ[r];
            const float* Ai = g_AB + (size_t)(b * NSEL + i) * (2 * HID);
            const float* Bj = g_AB + (size_t)(b * NSEL + j) * (2 * HID) + HID;
            #pragma unroll
            for (int t = 0; t < 7; ++t) {
                int nt_g = wn + 4 * t;
                if (nt_g < NTILES) {
                    int col = nt_g * 8 + 2 * l4;
                    float2 ai = *(const float2*)(Ai + col);
                    float2 bj = *(const float2*)(Bj + col);
                    float v0 = acc[mt][t][half * 2 + 0] + ai.x + bj.x + b1s[col];
                    float v1 = acc[mt][t][half * 2 + 1] + ai.y + bj.y + b1s[col + 1];
                    __nv_bfloat162 o = __floats2bfloat162_rn(fmaxf(v0, 0.f), fmaxf(v1, 0.f));
                    *(uint32_t*)&Hs[r * HS_STRIDE + col] = *(uint32_t*)&o;
                }
            }
        }
    }
    // zero pad cols [200,224)
    for (int e = tid; e < MTILE * 12; e += 256) {
        int r = e / 12, cc = HID + (e % 12) * 2;
        *(uint32_t*)&Hs[r * HS_STRIDE + cc] = 0u;
    }
    __syncthreads();

    #pragma unroll
    for (int mt = 0; mt < 4; ++mt)
        #pragma unroll
        for (int t = 0; t < 7; ++t)
            #pragma unroll
            for (int v = 0; v < 4; ++v) acc[mt][t][v] = 0.f;

    // ---------------- layer-2 mainloop (A from Hs) ----------------
    {
        #pragma unroll
        for (int u = 0; u < 4; ++u) {
            int e = tid + u * 256;
            if (e < HID * 4) {
                int n = e >> 2, seg = e & 3;
                cpasync16(ws_base[0] + n * (XS_STRIDE * 2) + seg * 16,
                          g_W2t + (size_t)n * K2PAD + seg * 8);
            }
        }
        cpasync_commit();
        cpasync_wait0();
        __syncthreads();
    }
    for (int c = 0; c < L2C; ++c) {
        uint32_t wsb = ws_base[c & 1];
        int nb = (c + 1) & 1;
        if (c + 1 < L2C) {
            int c0n = (c + 1) * 32;
            #pragma unroll
            for (int u = 0; u < 4; ++u) {
                int e = tid + u * 256;
                if (e < HID * 4) {
                    int n = e >> 2, seg = e & 3;
                    cpasync16(ws_base[nb] + n * (XS_STRIDE * 2) + seg * 16,
                              g_W2t + (size_t)n * K2PAD + c0n + seg * 8);
                }
            }
            cpasync_commit();
        }
        int c0 = c * 32;
        #pragma unroll
        for (int ks = 0; ks < 2; ++ks) {
            int kb = ks * 16;
            uint32_t a[4][4];
            #pragma unroll
            for (int mt = 0; mt < 4; ++mt)
                ldsm_x4(a[mt], hs_base + ((rowA + mt * 16) * HS_STRIDE + c0 + kb + colhA) * 2);
            #pragma unroll
            for (int t = 0; t < 7; ++t) {
                int nt_g = wn + 4 * t;
                if (nt_g < NTILES) {
                    uint32_t bb[2];
                    ldsm_x2(bb, wsb + ((nt_g * 8 + rowB) * XS_STRIDE + kb + colhB) * 2);
                    #pragma unroll
                    for (int mt = 0; mt < 4; ++mt)
                        mma16816(acc[mt][t], a[mt], bb);
                }
            }
        }
        cpasync_wait0();
        __syncthreads();
    }

    // ---------------- scoring epilogue ----------------
    #pragma unroll
    for (int mt = 0; mt < 4; ++mt) {
        #pragma unroll
        for (int half = 0; half < 2; ++half) {
            float sp = 0.f;
            #pragma unroll
            for (int t = 0; t < 7; ++t) {
                int nt_g = wn + 4 * t;
                if (nt_g < NTILES) {
                    int col = nt_g * 8 + 2 * l4;
                    float h0 = fmaxf(acc[mt][t][half * 2 + 0] + b2s[col], 0.f);
                    float h1 = fmaxf(acc[mt][t][half * 2 + 1] + b2s[col + 1], 0.f);
                    sp = fmaf(h0, W3s[col], sp);
                    sp = fmaf(h1, W3s[col + 1], sp);
                }
            }
            sp += __shfl_xor_sync(0xFFFFFFFFu, sp, 1);
            sp += __shfl_xor_sync(0xFFFFFFFFu, sp, 2);
            if (l4 == 0) {
                int r = wm * 64 + mt * 16 + q + 8 * half;
                sred[r][wn] = sp;
            }
        }
    }
    __syncthreads();
    if (tid < MTILE) {
        float s = sred[tid][0] + sred[tid][1] + sred[tid][2] + sred[tid][3] + b3[0];
        int i = sII[tid], j = sJJ[tid];
        g_S[((size_t)b * NSEL + i) * NSEL + j] = s;
    }
}

// ---------------- row softmax + fill ----------------
__global__ void k_soft(float* __restrict__ out) {
    int bn = blockIdx.x;
    int i = bn % NSEL;
    const float* Srow = g_S + (size_t)bn * NSEL;
    float* orow = out + (size_t)bn * NSEL;
    __shared__ float red[256];
    int tid = threadIdx.x;

    float mx = -1e30f;
    for (int j = tid; j <= i; j += 256) {
        float l = (j == i) ? 0.f : Srow[j];
        mx = fmaxf(mx, l);
    }
    red[tid] = mx; __syncthreads();
    for (int s = 128; s > 0; s >>= 1) {
        if (tid < s) red[tid] = fmaxf(red[tid], red[tid + s]);
        __syncthreads();
    }
    mx = red[0]; __syncthreads();

    float sum = 0.f;
    for (int j = tid; j <= i; j += 256) {
        float l = (j == i) ? 0.f : Srow[j];
        sum += __expf(l - mx);
    }
    red[tid] = sum; __syncthreads();
    for (int s = 128; s > 0; s >>= 1) {
        if (tid < s) red[tid] += red[tid + s];
        __syncthreads();
    }
    sum = red[0];
    float inv = 1.0f / sum;

    for (int j = tid; j < NSEL; j += 256) {
        if (j <= i) {
            float l = (j == i) ? 0.f : Srow[j];
            orow[j] = __expf(l - mx) * inv;
        } else {
            orow[j] = -1000.0f;
        }
    }
}

// ---------------- launch ----------------
extern "C" void kernel_launch(void* const* d_in, const int* in_sizes, int n_in,
                              void* d_out, int out_size) {
    const float* emb = (const float*)d_in[0];
    const int*   idx = (const int*)  d_in[1];
    const float* W1  = (const float*)d_in[2];
    const float* b1  = (const float*)d_in[3];
    const float* W2  = (const float*)d_in[4];
    const float* b2  = (const float*)d_in[5];
    const float* W3  = (const float*)d_in[6];
    const float* b3  = (const float*)d_in[7];
    float* out = (float*)d_out;

    static int configured = 0;
    if (!configured) {
        cudaFuncSetAttribute(k_fused, cudaFuncAttributeMaxDynamicSharedMemorySize,
                             DYN_BYTES);
        configured = 1;
    }

    k_prep<<<PREP_BLKS, 256>>>(emb, idx, W1, W2);
    k_ab<<<dim3(16, 7), 256>>>(W1);
    k_fused<<<dim3(NT1, BATCH), 256, DYN_BYTES>>>(b1, b2, W3, b3);
    k_soft<<<BATCH * NSEL, 256>>>(out);
}

// round 8
// speedup vs baseline: 6.6691x; 1.1297x over previous
#include <cuda_runtime.h>
#include <cuda_bf16.h>
#include <math.h>
#include <stdint.h>

#define BATCH 4
#define TLEN  4096
#define DIM   768
#define NSEL  256
#define HID   200
#define NPAIR 32640          // NSEL*(NSEL-1)/2
#define MTILE 64             // pairs per CTA
#define NT1   510            // NPAIR / MTILE
#define K2PAD 224            // padded K for layer 2 (7 chunks of 32)
#define XS_STRIDE 40         // bf16 elems per smem row (80B)
#define HS_STRIDE 232        // bf16 elems per Hs row (464B)
#define L1C   (DIM / 32)     // 24 chunks
#define L2C   (K2PAD / 32)   // 7 chunks
#define NTILES 25            // 200/8 n-tiles

// dynamic smem layout (bytes)
#define XS0_OFF 0
#define XS1_OFF (MTILE * XS_STRIDE * 2)                 // 5120
#define WS0_OFF (2 * MTILE * XS_STRIDE * 2)             // 10240
#define WS1_OFF (WS0_OFF + HID * XS_STRIDE * 2)         // 26240
#define HS_OFF  (WS1_OFF + HID * XS_STRIDE * 2)         // 42240
#define DYN_BYTES (HS_OFF + MTILE * HS_STRIDE * 2)      // 71936

// ---------------- device scratch ----------------
__device__ float          g_E  [BATCH * NSEL * DIM];
__device__ float          g_AB [BATCH * NSEL * 2 * HID];
__device__ __nv_bfloat16  g_W1t[HID * DIM];             // [h][d]
__device__ __nv_bfloat16  g_W2t[HID * K2PAD];           // [h][k], k>=200 zero
__device__ float          g_S  [BATCH * NSEL * NSEL];
__device__ int            g_II [NPAIR];
__device__ int            g_JJ [NPAIR];

// ---------------- helpers ----------------
__device__ __forceinline__ void mma16816(float* c, const uint32_t* a, const uint32_t* b) {
    asm volatile(
        "mma.sync.aligned.m16n8k16.row.col.f32.bf16.bf16.f32 "
        "{%0,%1,%2,%3}, {%4,%5,%6,%7}, {%8,%9}, {%0,%1,%2,%3};"
        : "+f"(c[0]), "+f"(c[1]), "+f"(c[2]), "+f"(c[3])
        : "r"(a[0]), "r"(a[1]), "r"(a[2]), "r"(a[3]), "r"(b[0]), "r"(b[1]));
}
__device__ __forceinline__ void ldsm_x4(uint32_t* r, uint32_t addr) {
    asm volatile("ldmatrix.sync.aligned.m8n8.x4.shared.b16 {%0,%1,%2,%3}, [%4];"
                 : "=r"(r[0]), "=r"(r[1]), "=r"(r[2]), "=r"(r[3]) : "r"(addr));
}
__device__ __forceinline__ void ldsm_x2(uint32_t* r, uint32_t addr) {
    asm volatile("ldmatrix.sync.aligned.m8n8.x2.shared.b16 {%0,%1}, [%2];"
                 : "=r"(r[0]), "=r"(r[1]) : "r"(addr));
}
__device__ __forceinline__ void cpasync16(uint32_t smem_addr, const void* gsrc) {
    asm volatile("cp.async.cg.shared.global [%0], [%1], 16;"
                 :: "r"(smem_addr), "l"(gsrc) : "memory");
}
__device__ __forceinline__ void cpasync_commit() {
    asm volatile("cp.async.commit_group;" ::: "memory");
}
__device__ __forceinline__ void cpasync_wait0() {
    asm volatile("cp.async.wait_group 0;" ::: "memory");
}

// ---------------- fused prep: pairs + gather + W1t + W2t ----------------
#define PREP_PAIRS 128
#define PREP_GATH  (BATCH * NSEL)                       // 1024
#define PREP_W1    ((HID * DIM + 255) / 256)            // 600
#define PREP_W2    ((HID * K2PAD + 255) / 256)          // 175
#define PREP_BLKS  (PREP_PAIRS + PREP_GATH + PREP_W1 + PREP_W2)

__global__ void k_prep(const float* __restrict__ emb, const int* __restrict__ idx,
                       const float* __restrict__ W1, const float* __restrict__ W2) {
    int blk = blockIdx.x;
    int tid = threadIdx.x;
    if (blk < PREP_PAIRS) {
        int p = blk * 256 + tid;
        if (p < NPAIR) {
            int i = (int)((1.0f + sqrtf(1.0f + 8.0f * (float)p)) * 0.5f);
            while (i > 1 && i * (i - 1) / 2 > p) --i;
            while ((i + 1) * i / 2 <= p) ++i;
            g_II[p] = i;
            g_JJ[p] = p - i * (i - 1) / 2;
        }
        return;
    }
    blk -= PREP_PAIRS;
    if (blk < PREP_GATH) {
        int b = blk / NSEL, n = blk % NSEL;
        int t = idx[b * NSEL + n];
        const float4* src = (const float4*)(emb + ((size_t)b * TLEN + t) * DIM);
        float4* dst = (float4*)(g_E + (size_t)blk * DIM);
        if (tid < DIM / 4) dst[tid] = src[tid];
        return;
    }
    blk -= PREP_GATH;
    if (blk < PREP_W1) {
        int e = blk * 256 + tid;
        if (e < HID * DIM) {
            int h = e / DIM, d = e % DIM;
            g_W1t[e] = __float2bfloat16(W1[(size_t)(2 * DIM + d) * HID + h]);
        }
        return;
    }
    blk -= PREP_W1;
    {
        int e = blk * 256 + tid;
        if (e < HID * K2PAD) {
            int h = e / K2PAD, k = e % K2PAD;
            float v = (k < HID) ? W2[(size_t)k * HID + h] : 0.f;
            g_W2t[e] = __float2bfloat16(v);
        }
    }
}

// ---------------- exact A/B partials (fp32 SIMT, small) ----------------
__global__ void k_ab(const float* __restrict__ W1) {
    __shared__ __align__(16) float As[16][64 + 4];
    __shared__ __align__(16) float Bs[16][64 + 4];
    int bm = blockIdx.x * 64, bn = blockIdx.y * 64;
    int tx = threadIdx.x % 16, ty = threadIdx.x / 16;
    float acc[4][4] = {};
    for (int k0 = 0; k0 < DIM; k0 += 16) {
        for (int t = threadIdx.x; t < 1024; t += 256) {
            int k = t % 16, m = t / 16;
            As[k][m] = g_E[(size_t)(bm + m) * DIM + k0 + k];
        }
        for (int t = threadIdx.x; t < 1024; t += 256) {
            int n = t % 64, k = t / 64;
            int c = bn + n;
            float v = 0.f;
            if (c < 2 * HID) {
                int half = c / HID, h = c - half * HID;
                v = W1[(size_t)(half * DIM + k0 + k) * HID + h];
            }
            Bs[k][n] = v;
        }
        __syncthreads();
        #pragma unroll
        for (int k = 0; k < 16; ++k) {
            float a[4], bb[4];
            #pragma unroll
            for (int u = 0; u < 4; ++u) a[u] = As[k][ty * 4 + u];
            #pragma unroll
            for (int v = 0; v < 4; ++v) bb[v] = Bs[k][tx * 4 + v];
            #pragma unroll
            for (int u = 0; u < 4; ++u)
                #pragma unroll
                for (int v = 0; v < 4; ++v)
                    acc[u][v] = fmaf(a[u], bb[v], acc[u][v]);
        }
        __syncthreads();
    }
    #pragma unroll
    for (int u = 0; u < 4; ++u)
        #pragma unroll
        for (int v = 0; v < 4; ++v) {
            int c = bn + tx * 4 + v;
            if (c < 2 * HID)
                g_AB[(size_t)(bm + ty * 4 + u) * (2 * HID) + c] = acc[u][v];
        }
}

// ================= fused MLP =================
// CTA: 64 pairs, 256 threads, 2 CTAs/SM.
// 8 warps: wm = wid&1 -> 32 rows (2 mt of 16), wn = wid>>1 -> 7 n-tiles (nt_g = wn + 4t < 25).
__global__ __launch_bounds__(256, 2)
void k_fused(const float* __restrict__ b1, const float* __restrict__ b2,
             const float* __restrict__ W3, const float* __restrict__ b3) {
    extern __shared__ __align__(16) char dynsm[];
    __nv_bfloat16* XsBuf[2] = { (__nv_bfloat16*)(dynsm + XS0_OFF),
                                (__nv_bfloat16*)(dynsm + XS1_OFF) };
    uint32_t dynbase = (uint32_t)__cvta_generic_to_shared(dynsm);
    uint32_t xs_base[2] = { dynbase + XS0_OFF, dynbase + XS1_OFF };
    uint32_t ws_base[2] = { dynbase + WS0_OFF, dynbase + WS1_OFF };
    uint32_t hs_base = dynbase + HS_OFF;
    __nv_bfloat16* Hs = (__nv_bfloat16*)(dynsm + HS_OFF);

    __shared__ int sII[MTILE], sJJ[MTILE];
    __shared__ float b1s[HID], b2s[HID], W3s[HID];
    __shared__ float sred[MTILE][4];

    int tid = threadIdx.x;
    int b = blockIdx.y;
    int p0 = blockIdx.x * MTILE;
    if (tid < MTILE) { sII[tid] = g_II[p0 + tid]; sJJ[tid] = g_JJ[p0 + tid]; }
    if (tid < HID) { b1s[tid] = b1[tid]; b2s[tid] = b2[tid]; W3s[tid] = W3[tid]; }

    const float* Eb = g_E + (size_t)b * NSEL * DIM;
    int wid = tid / 32, lane = tid % 32;
    int wm = wid & 1, wn = wid >> 1;
    int q = lane >> 2, l4 = lane & 3;

    // ldmatrix per-thread address components
    int rowA = wm * 32 + (lane & 15);          // + mt*16
    int colhA = (lane >> 4) * 8;               // elems
    int rowB = lane & 7;                       // + nt_g*8
    int colhB = ((lane >> 3) & 1) * 8;

    // X-fill coordinates (4 u32 per thread: 64 rows x 16 u32)
    int xr[4], xk[4];
    #pragma unroll
    for (int u = 0; u < 4; ++u) {
        int e = tid + u * 256;
        xr[u] = e >> 4;
        xk[u] = (e & 15) * 2;
    }
    __syncthreads();

    float acc[2][7][4];
    #pragma unroll
    for (int mt = 0; mt < 2; ++mt)
        #pragma unroll
        for (int t = 0; t < 7; ++t)
            #pragma unroll
            for (int v = 0; v < 4; ++v) acc[mt][t][v] = 0.f;

    // ---------------- layer-1 mainloop ----------------
    {
        #pragma unroll
        for (int u = 0; u < 4; ++u) {
            const float2 xi = *(const float2*)(Eb + (size_t)sII[xr[u]] * DIM + xk[u]);
            const float2 xj = *(const float2*)(Eb + (size_t)sJJ[xr[u]] * DIM + xk[u]);
            __nv_bfloat162 v = __floats2bfloat162_rn(xi.x * xj.x, xi.y * xj.y);
            *(uint32_t*)&XsBuf[0][xr[u] * XS_STRIDE + xk[u]] = *(uint32_t*)&v;
        }
        #pragma unroll
        for (int u = 0; u < 4; ++u) {
            int e = tid + u * 256;
            if (e < HID * 4) {
                int n = e >> 2, seg = e & 3;
                cpasync16(ws_base[0] + n * (XS_STRIDE * 2) + seg * 16,
                          g_W1t + (size_t)n * DIM + seg * 8);
            }
        }
        cpasync_commit();
        cpasync_wait0();
        __syncthreads();
    }

    for (int c = 0; c < L1C; ++c) {
        uint32_t xsb = xs_base[c & 1];
        uint32_t wsb = ws_base[c & 1];
        int nb = (c + 1) & 1;
        bool more = (c + 1 < L1C);
        int c0n = (c + 1) * 32;

        if (more) {
            #pragma unroll
            for (int u = 0; u < 4; ++u) {
                int e = tid + u * 256;
                if (e < HID * 4) {
                    int n = e >> 2, seg = e & 3;
                    cpasync16(ws_base[nb] + n * (XS_STRIDE * 2) + seg * 16,
                              g_W1t + (size_t)n * DIM + c0n + seg * 8);
                }
            }
            cpasync_commit();
        }
        float2 pxi[4], pxj[4];
        if (more) {
            #pragma unroll
            for (int u = 0; u < 4; ++u) {
                pxi[u] = *(const float2*)(Eb + (size_t)sII[xr[u]] * DIM + c0n + xk[u]);
                pxj[u] = *(const float2*)(Eb + (size_t)sJJ[xr[u]] * DIM + c0n + xk[u]);
            }
        }
        #pragma unroll
        for (int ks = 0; ks < 2; ++ks) {
            int kb = ks * 16;
            uint32_t a[2][4];
            #pragma unroll
            for (int mt = 0; mt < 2; ++mt)
                ldsm_x4(a[mt], xsb + ((rowA + mt * 16) * XS_STRIDE + kb + colhA) * 2);
            #pragma unroll
            for (int t = 0; t < 7; ++t) {
                int nt_g = wn + 4 * t;
                if (nt_g < NTILES) {
                    uint32_t bb[2];
                    ldsm_x2(bb, wsb + ((nt_g * 8 + rowB) * XS_STRIDE + kb + colhB) * 2);
                    #pragma unroll
                    for (int mt = 0; mt < 2; ++mt)
                        mma16816(acc[mt][t], a[mt], bb);
                }
            }
        }
        if (more) {
            #pragma unroll
            for (int u = 0; u < 4; ++u) {
                __nv_bfloat162 v = __floats2bfloat162_rn(pxi[u].x * pxj[u].x,
                                                         pxi[u].y * pxj[u].y);
                *(uint32_t*)&XsBuf[nb][xr[u] * XS_STRIDE + xk[u]] = *(uint32_t*)&v;
            }
        }
        cpasync_wait0();
        __syncthreads();
    }

    // ---------------- layer-1 epilogue -> Hs ----------------
    #pragma unroll
    for (int mt = 0; mt < 2; ++mt) {
        #pragma unroll
        for (int half = 0; half < 2; ++half) {
            int r = wm * 32 + mt * 16 + q + 8 * half;
            int i = sII[r], j = sJJ[r];
            const float* Ai = g_AB + (size_t)(b * NSEL + i) * (2 * HID);
            const float* Bj = g_AB + (size_t)(b * NSEL + j) * (2 * HID) + HID;
            #pragma unroll
            for (int t = 0; t < 7; ++t) {
                int nt_g = wn + 4 * t;
                if (nt_g < NTILES) {
                    int col = nt_g * 8 + 2 * l4;
                    float2 ai = *(const float2*)(Ai + col);
                    float2 bj = *(const float2*)(Bj + col);
                    float v0 = acc[mt][t][half * 2 + 0] + ai.x + bj.x + b1s[col];
                    float v1 = acc[mt][t][half * 2 + 1] + ai.y + bj.y + b1s[col + 1];
                    __nv_bfloat162 o = __floats2bfloat162_rn(fmaxf(v0, 0.f), fmaxf(v1, 0.f));
                    *(uint32_t*)&Hs[r * HS_STRIDE + col] = *(uint32_t*)&o;
                }
            }
        }
    }
    // zero pad cols [200,224)
    for (int e = tid; e < MTILE * 12; e += 256) {
        int r = e / 12, cc = HID + (e % 12) * 2;
        *(uint32_t*)&Hs[r * HS_STRIDE + cc] = 0u;
    }
    __syncthreads();

    #pragma unroll
    for (int mt = 0; mt < 2; ++mt)
        #pragma unroll
        for (int t = 0; t < 7; ++t)
            #pragma unroll
            for (int v = 0; v < 4; ++v) acc[mt][t][v] = 0.f;

    // ---------------- layer-2 mainloop (A from Hs) ----------------
    {
        #pragma unroll
        for (int u = 0; u < 4; ++u) {
            int e = tid + u * 256;
            if (e < HID * 4) {
                int n = e >> 2, seg = e & 3;
                cpasync16(ws_base[0] + n * (XS_STRIDE * 2) + seg * 16,
                          g_W2t + (size_t)n * K2PAD + seg * 8);
            }
        }
        cpasync_commit();
        cpasync_wait0();
        __syncthreads();
    }
    for (int c = 0; c < L2C; ++c) {
        uint32_t wsb = ws_base[c & 1];
        int nb = (c + 1) & 1;
        if (c + 1 < L2C) {
            int c0n = (c + 1) * 32;
            #pragma unroll
            for (int u = 0; u < 4; ++u) {
                int e = tid + u * 256;
                if (e < HID * 4) {
                    int n = e >> 2, seg = e & 3;
                    cpasync16(ws_base[nb] + n * (XS_STRIDE * 2) + seg * 16,
                              g_W2t + (size_t)n * K2PAD + c0n + seg * 8);
                }
            }
            cpasync_commit();
        }
        int c0 = c * 32;
        #pragma unroll
        for (int ks = 0; ks < 2; ++ks) {
            int kb = ks * 16;
            uint32_t a[2][4];
            #pragma unroll
            for (int mt = 0; mt < 2; ++mt)
                ldsm_x4(a[mt], hs_base + ((rowA + mt * 16) * HS_STRIDE + c0 + kb + colhA) * 2);
            #pragma unroll
            for (int t = 0; t < 7; ++t) {
                int nt_g = wn + 4 * t;
                if (nt_g < NTILES) {
                    uint32_t bb[2];
                    ldsm_x2(bb, wsb + ((nt_g * 8 + rowB) * XS_STRIDE + kb + colhB) * 2);
                    #pragma unroll
                    for (int mt = 0; mt < 2; ++mt)
                        mma16816(acc[mt][t], a[mt], bb);
                }
            }
        }
        cpasync_wait0();
        __syncthreads();
    }

    // ---------------- scoring epilogue ----------------
    #pragma unroll
    for (int mt = 0; mt < 2; ++mt) {
        #pragma unroll
        for (int half = 0; half < 2; ++half) {
            float sp = 0.f;
            #pragma unroll
            for (int t = 0; t < 7; ++t) {
                int nt_g = wn + 4 * t;
                if (nt_g < NTILES) {
                    int col = nt_g * 8 + 2 * l4;
                    float h0 = fmaxf(acc[mt][t][half * 2 + 0] + b2s[col], 0.f);
                    float h1 = fmaxf(acc[mt][t][half * 2 + 1] + b2s[col + 1], 0.f);
                    sp = fmaf(h0, W3s[col], sp);
                    sp = fmaf(h1, W3s[col + 1], sp);
                }
            }
            sp += __shfl_xor_sync(0xFFFFFFFFu, sp, 1);
            sp += __shfl_xor_sync(0xFFFFFFFFu, sp, 2);
            if (l4 == 0) {
                int r = wm * 32 + mt * 16 + q + 8 * half;
                sred[r][wn] = sp;
            }
        }
    }
    __syncthreads();
    if (tid < MTILE) {
        float s = sred[tid][0] + sred[tid][1] + sred[tid][2] + sred[tid][3] + b3[0];
        int i = sII[tid], j = sJJ[tid];
        g_S[((size_t)b * NSEL + i) * NSEL + j] = s;
    }
}

// ---------------- row softmax + fill ----------------
__global__ void k_soft(float* __restrict__ out) {
    int bn = blockIdx.x;
    int i = bn % NSEL;
    const float* Srow = g_S + (size_t)bn * NSEL;
    float* orow = out + (size_t)bn * NSEL;
    __shared__ float red[256];
    int tid = threadIdx.x;

    float mx = -1e30f;
    for (int j = tid; j <= i; j += 256) {
        float l = (j == i) ? 0.f : Srow[j];
        mx = fmaxf(mx, l);
    }
    red[tid] = mx; __syncthreads();
    for (int s = 128; s > 0; s >>= 1) {
        if (tid < s) red[tid] = fmaxf(red[tid], red[tid + s]);
        __syncthreads();
    }
    mx = red[0]; __syncthreads();

    float sum = 0.f;
    for (int j = tid; j <= i; j += 256) {
        float l = (j == i) ? 0.f : Srow[j];
        sum += __expf(l - mx);
    }
    red[tid] = sum; __syncthreads();
    for (int s = 128; s > 0; s >>= 1) {
        if (tid < s) red[tid] += red[tid + s];
        __syncthreads();
    }
    sum = red[0];
    float inv = 1.0f / sum;

    for (int j = tid; j < NSEL; j += 256) {
        if (j <= i) {
            float l = (j == i) ? 0.f : Srow[j];
            orow[j] = __expf(l - mx) * inv;
        } else {
            orow[j] = -1000.0f;
        }
    }
}

// ---------------- launch ----------------
extern "C" void kernel_launch(void* const* d_in, const int* in_sizes, int n_in,
                              void* d_out, int out_size) {
    const float* emb = (const float*)d_in[0];
    const int*   idx = (const int*)  d_in[1];
    const float* W1  = (const float*)d_in[2];
    const float* b1  = (const float*)d_in[3];
    const float* W2  = (const float*)d_in[4];
    const float* b2  = (const float*)d_in[5];
    const float* W3  = (const float*)d_in[6];
    const float* b3  = (const float*)d_in[7];
    float* out = (float*)d_out;

    static int configured = 0;
    if (!configured) {
        cudaFuncSetAttribute(k_fused, cudaFuncAttributeMaxDynamicSharedMemorySize,
                             DYN_BYTES);
        configured = 1;
    }

    k_prep<<<PREP_BLKS, 256>>>(emb, idx, W1, W2);
    k_ab<<<dim3(16, 7), 256>>>(W1);
    k_fused<<<dim3(NT1, BATCH), 256, DYN_BYTES>>>(b1, b2, W3, b3);
    k_soft<<<BATCH * NSEL, 256>>>(out);
}

// round 9
// speedup vs baseline: 6.9650x; 1.0444x over previous
#include <cuda_runtime.h>
#include <cuda_bf16.h>
#include <math.h>
#include <stdint.h>

#define BATCH 4
#define TLEN  4096
#define DIM   768
#define NSEL  256
#define HID   200
#define NPAIR 32640
#define MTILE 64             // pairs per CTA (8x8 token block)
#define NB8   32             // token blocks per batch (256/8)
#define NBLK  528            // NB8*(NB8+1)/2
#define K2PAD 224            // padded K for layer 2 (7 chunks of 32)
#define XS_STRIDE 40         // bf16 elems per smem row (80B)
#define HS_STRIDE 232        // bf16 elems per Hs row (464B)
#define L1C   (DIM / 32)     // 24 chunks
#define L2C   (K2PAD / 32)   // 7 chunks
#define NTILES 25            // 200/8 n-tiles

// dynamic smem layout (bytes)
#define XS0_OFF 0                      // 5120
#define XS1_OFF 5120                   // 5120
#define WS0_OFF 10240                  // 16000
#define WS1_OFF 26240                  // 16000
#define ES0_OFF 42240                  // 2048 (16 rows x 32 fp32)
#define ES1_OFF 44288                  // 2048
#define AB_OFF  46336                  // 12800 (16 rows x 200 fp32)
#define HS_OFF  59136                  // 29696
#define DYN_BYTES 88832

// ---------------- device scratch ----------------
__device__ float          g_E  [BATCH * NSEL * DIM];
__device__ float          g_AB [BATCH * NSEL * 2 * HID];
__device__ __nv_bfloat16  g_W1t[HID * DIM];             // [h][d]
__device__ __nv_bfloat16  g_W2t[HID * K2PAD];           // [h][k], k>=200 zero
__device__ float          g_S  [BATCH * NSEL * NSEL];

// ---------------- helpers ----------------
__device__ __forceinline__ void mma16816(float* c, const uint32_t* a, const uint32_t* b) {
    asm volatile(
        "mma.sync.aligned.m16n8k16.row.col.f32.bf16.bf16.f32 "
        "{%0,%1,%2,%3}, {%4,%5,%6,%7}, {%8,%9}, {%0,%1,%2,%3};"
        : "+f"(c[0]), "+f"(c[1]), "+f"(c[2]), "+f"(c[3])
        : "r"(a[0]), "r"(a[1]), "r"(a[2]), "r"(a[3]), "r"(b[0]), "r"(b[1]));
}
__device__ __forceinline__ void ldsm_x4(uint32_t* r, uint32_t addr) {
    asm volatile("ldmatrix.sync.aligned.m8n8.x4.shared.b16 {%0,%1,%2,%3}, [%4];"
                 : "=r"(r[0]), "=r"(r[1]), "=r"(r[2]), "=r"(r[3]) : "r"(addr));
}
__device__ __forceinline__ void ldsm_x2(uint32_t* r, uint32_t addr) {
    asm volatile("ldmatrix.sync.aligned.m8n8.x2.shared.b16 {%0,%1}, [%2];"
                 : "=r"(r[0]), "=r"(r[1]) : "r"(addr));
}
__device__ __forceinline__ void cpasync16(uint32_t smem_addr, const void* gsrc) {
    asm volatile("cp.async.cg.shared.global [%0], [%1], 16;"
                 :: "r"(smem_addr), "l"(gsrc) : "memory");
}
__device__ __forceinline__ void cpasync_commit() {
    asm volatile("cp.async.commit_group;" ::: "memory");
}
__device__ __forceinline__ void cpasync_wait0() {
    asm volatile("cp.async.wait_group 0;" ::: "memory");
}

// ---------------- fused prep: gather + W1t + W2t ----------------
#define PREP_GATH  (BATCH * NSEL)                       // 1024
#define PREP_W1    ((HID * DIM + 255) / 256)            // 600
#define PREP_W2    ((HID * K2PAD + 255) / 256)          // 175
#define PREP_BLKS  (PREP_GATH + PREP_W1 + PREP_W2)

__global__ void k_prep(const float* __restrict__ emb, const int* __restrict__ idx,
                       const float* __restrict__ W1, const float* __restrict__ W2) {
    int blk = blockIdx.x;
    int tid = threadIdx.x;
    if (blk < PREP_GATH) {
        int b = blk / NSEL, n = blk % NSEL;
        int t = idx[b * NSEL + n];
        const float4* src = (const float4*)(emb + ((size_t)b * TLEN + t) * DIM);
        float4* dst = (float4*)(g_E + (size_t)blk * DIM);
        if (tid < DIM / 4) dst[tid] = src[tid];
        return;
    }
    blk -= PREP_GATH;
    if (blk < PREP_W1) {
        int e = blk * 256 + tid;
        if (e < HID * DIM) {
            int h = e / DIM, d = e % DIM;
            g_W1t[e] = __float2bfloat16(W1[(size_t)(2 * DIM + d) * HID + h]);
        }
        return;
    }
    blk -= PREP_W1;
    {
        int e = blk * 256 + tid;
        if (e < HID * K2PAD) {
            int h = e / K2PAD, k = e % K2PAD;
            float v = (k < HID) ? W2[(size_t)k * HID + h] : 0.f;
            g_W2t[e] = __float2bfloat16(v);
        }
    }
}

// ---------------- exact A/B partials (fp32 SIMT, small) ----------------
__global__ void k_ab(const float* __restrict__ W1) {
    __shared__ __align__(16) float As[16][64 + 4];
    __shared__ __align__(16) float Bs[16][64 + 4];
    int bm = blockIdx.x * 64, bn = blockIdx.y * 64;
    int tx = threadIdx.x % 16, ty = threadIdx.x / 16;
    float acc[4][4] = {};
    for (int k0 = 0; k0 < DIM; k0 += 16) {
        for (int t = threadIdx.x; t < 1024; t += 256) {
            int k = t % 16, m = t / 16;
            As[k][m] = g_E[(size_t)(bm + m) * DIM + k0 + k];
        }
        for (int t = threadIdx.x; t < 1024; t += 256) {
            int n = t % 64, k = t / 64;
            int c = bn + n;
            float v = 0.f;
            if (c < 2 * HID) {
                int half = c / HID, h = c - half * HID;
                v = W1[(size_t)(half * DIM + k0 + k) * HID + h];
            }
            Bs[k][n] = v;
        }
        __syncthreads();
        #pragma unroll
        for (int k = 0; k < 16; ++k) {
            float a[4], bb[4];
            #pragma unroll
            for (int u = 0; u < 4; ++u) a[u] = As[k][ty * 4 + u];
            #pragma unroll
            for (int v = 0; v < 4; ++v) bb[v] = Bs[k][tx * 4 + v];
            #pragma unroll
            for (int u = 0; u < 4; ++u)
                #pragma unroll
                for (int v = 0; v < 4; ++v)
                    acc[u][v] = fmaf(a[u], bb[v], acc[u][v]);
        }
        __syncthreads();
    }
    #pragma unroll
    for (int u = 0; u < 4; ++u)
        #pragma unroll
        for (int v = 0; v < 4; ++v) {
            int c = bn + tx * 4 + v;
            if (c < 2 * HID)
                g_AB[(size_t)(bm + ty * 4 + u) * (2 * HID) + c] = acc[u][v];
        }
}

// ================= fused MLP (pair-blocked) =================
// CTA = token block (bi, bj), bi >= bj; pair row r = ri*8+rj -> (i,j) = (bi*8+ri, bj*8+rj).
// 8 warps: wm = wid&1 -> 32 rows, wn = wid>>1 -> 7 n-tiles (nt_g = wn + 4t < 25).
__global__ __launch_bounds__(256, 2)
void k_fused(const float* __restrict__ b1, const float* __restrict__ b2,
             const float* __restrict__ W3, const float* __restrict__ b3) {
    extern __shared__ __align__(16) char dynsm[];
    uint32_t dynbase = (uint32_t)__cvta_generic_to_shared(dynsm);
    uint32_t xs_base[2] = { dynbase + XS0_OFF, dynbase + XS1_OFF };
    uint32_t ws_base[2] = { dynbase + WS0_OFF, dynbase + WS1_OFF };
    uint32_t es_base[2] = { dynbase + ES0_OFF, dynbase + ES1_OFF };
    uint32_t ab_base = dynbase + AB_OFF;
    uint32_t hs_base = dynbase + HS_OFF;
    __nv_bfloat16* XsBuf[2] = { (__nv_bfloat16*)(dynsm + XS0_OFF),
                                (__nv_bfloat16*)(dynsm + XS1_OFF) };
    float* EsBuf[2] = { (float*)(dynsm + ES0_OFF), (float*)(dynsm + ES1_OFF) };
    float* sAB = (float*)(dynsm + AB_OFF);              // [16][200]
    __nv_bfloat16* Hs = (__nv_bfloat16*)(dynsm + HS_OFF);

    __shared__ float b1s[HID], b2s[HID], W3s[HID];
    __shared__ float sred[MTILE][4];

    int tid = threadIdx.x;
    int b = blockIdx.y;

    // decode token block (bi, bj), bi >= bj
    int tb = blockIdx.x;
    int bi = (int)((sqrtf(8.0f * (float)tb + 1.0f) - 1.0f) * 0.5f);
    while (bi * (bi + 1) / 2 > tb) --bi;
    while ((bi + 1) * (bi + 2) / 2 <= tb) ++bi;
    int bj = tb - bi * (bi + 1) / 2;

    if (tid < HID) { b1s[tid] = b1[tid]; b2s[tid] = b2[tid]; W3s[tid] = W3[tid]; }

    const float* Eb = g_E + (size_t)b * NSEL * DIM;
    int wid = tid / 32, lane = tid % 32;
    int wm = wid & 1, wn = wid >> 1;
    int q = lane >> 2, l4 = lane & 3;

    // ldmatrix per-thread address components
    int rowA = wm * 32 + (lane & 15);          // + mt*16
    int colhA = (lane >> 4) * 8;
    int rowB = lane & 7;                       // + nt_g*8
    int colhB = ((lane >> 3) & 1) * 8;

    // E-chunk cp.async coords (tid < 128): row r of 16, seg of 8 (16B = 4 floats)
    int er = tid >> 3, eseg = tid & 7;
    int etok = (er < 8) ? (bi * 8 + er) : (bj * 8 + er - 8);
    const float* esrc_row = Eb + (size_t)etok * DIM + eseg * 4;
    uint32_t edst = (uint32_t)((er * 32 + eseg * 4) * 4);

    // X-build coords (4 u32 per thread): e = tid + 256u over 1024
    int xr[4], xk[4];
    #pragma unroll
    for (int u = 0; u < 4; ++u) {
        int e = tid + u * 256;
        xr[u] = e >> 4;
        xk[u] = (e & 15) * 2;
    }

    float acc[2][7][4];
    #pragma unroll
    for (int mt = 0; mt < 2; ++mt)
        #pragma unroll
        for (int t = 0; t < 7; ++t)
            #pragma unroll
            for (int v = 0; v < 4; ++v) acc[mt][t][v] = 0.f;

    // ---------------- prologue: AB + E(0) + W1(0) ----------------
    {
        // sAB: rows 0-7 = Ai(bi*8+r), rows 8-15 = Bj(bj*8+r)+HID.  800 segs of 16B.
        #pragma unroll
        for (int u = 0; u < 4; ++u) {
            int e = tid + u * 256;
            if (e < 800) {
                int row = e / 50, seg = e % 50;
                int tok = (row < 8) ? (bi * 8 + row) : (bj * 8 + row - 8);
                int foff = (row < 8) ? 0 : HID;
                cpasync16(ab_base + (row * HID + seg * 4) * 4,
                          g_AB + ((size_t)(b * NSEL + tok)) * (2 * HID) + foff + seg * 4);
            }
        }
        if (tid < 128)
            cpasync16(es_base[0] + edst, esrc_row);
        #pragma unroll
        for (int u = 0; u < 4; ++u) {
            int e = tid + u * 256;
            if (e < HID * 4) {
                int n = e >> 2, seg = e & 3;
                cpasync16(ws_base[0] + n * (XS_STRIDE * 2) + seg * 16,
                          g_W1t + (size_t)n * DIM + seg * 8);
            }
        }
        cpasync_commit();
        cpasync_wait0();
        __syncthreads();
        // build X(0) from Es[0]
        #pragma unroll
        for (int u = 0; u < 4; ++u) {
            int ri = xr[u] >> 3, rj = xr[u] & 7;
            const float2 xi = *(const float2*)&EsBuf[0][ri * 32 + xk[u]];
            const float2 xj = *(const float2*)&EsBuf[0][(8 + rj) * 32 + xk[u]];
            __nv_bfloat162 v = __floats2bfloat162_rn(xi.x * xj.x, xi.y * xj.y);
            *(uint32_t*)&XsBuf[0][xr[u] * XS_STRIDE + xk[u]] = *(uint32_t*)&v;
        }
        __syncthreads();
    }

    // ---------------- layer-1 mainloop ----------------
    for (int c = 0; c < L1C; ++c) {
        uint32_t xsb = xs_base[c & 1];
        uint32_t wsb = ws_base[c & 1];
        int nb = (c + 1) & 1;
        bool more = (c + 1 < L1C);
        int c0n = (c + 1) * 32;

        if (more) {
            if (tid < 128)
                cpasync16(es_base[nb] + edst, esrc_row + c0n);
            #pragma unroll
            for (int u = 0; u < 4; ++u) {
                int e = tid + u * 256;
                if (e < HID * 4) {
                    int n = e >> 2, seg = e & 3;
                    cpasync16(ws_base[nb] + n * (XS_STRIDE * 2) + seg * 16,
                              g_W1t + (size_t)n * DIM + c0n + seg * 8);
                }
            }
            cpasync_commit();
        }
        #pragma unroll
        for (int ks = 0; ks < 2; ++ks) {
            int kb = ks * 16;
            uint32_t a[2][4];
            #pragma unroll
            for (int mt = 0; mt < 2; ++mt)
                ldsm_x4(a[mt], xsb + ((rowA + mt * 16) * XS_STRIDE + kb + colhA) * 2);
            #pragma unroll
            for (int t = 0; t < 7; ++t) {
                int nt_g = wn + 4 * t;
                if (nt_g < NTILES) {
                    uint32_t bb[2];
                    ldsm_x2(bb, wsb + ((nt_g * 8 + rowB) * XS_STRIDE + kb + colhB) * 2);
                    #pragma unroll
                    for (int mt = 0; mt < 2; ++mt)
                        mma16816(acc[mt][t], a[mt], bb);
                }
            }
        }
        if (more) {
            cpasync_wait0();
            #pragma unroll
            for (int u = 0; u < 4; ++u) {
                int ri = xr[u] >> 3, rj = xr[u] & 7;
                const float2 xi = *(const float2*)&EsBuf[nb][ri * 32 + xk[u]];
                const float2 xj = *(const float2*)&EsBuf[nb][(8 + rj) * 32 + xk[u]];
                __nv_bfloat162 v = __floats2bfloat162_rn(xi.x * xj.x, xi.y * xj.y);
                *(uint32_t*)&XsBuf[nb][xr[u] * XS_STRIDE + xk[u]] = *(uint32_t*)&v;
            }
        }
        __syncthreads();
    }

    // ---------------- layer-1 epilogue -> Hs (AB from smem) ----------------
    #pragma unroll
    for (int mt = 0; mt < 2; ++mt) {
        #pragma unroll
        for (int half = 0; half < 2; ++half) {
            int r = wm * 32 + mt * 16 + q + 8 * half;
            int ri = r >> 3, rj = r & 7;
            #pragma unroll
            for (int t = 0; t < 7; ++t) {
                int nt_g = wn + 4 * t;
                if (nt_g < NTILES) {
                    int col = nt_g * 8 + 2 * l4;
                    float2 ai = *(const float2*)&sAB[ri * HID + col];
                    float2 bj = *(const float2*)&sAB[(8 + rj) * HID + col];
                    float v0 = acc[mt][t][half * 2 + 0] + ai.x + bj.x + b1s[col];
                    float v1 = acc[mt][t][half * 2 + 1] + ai.y + bj.y + b1s[col + 1];
                    __nv_bfloat162 o = __floats2bfloat162_rn(fmaxf(v0, 0.f), fmaxf(v1, 0.f));
                    *(uint32_t*)&Hs[r * HS_STRIDE + col] = *(uint32_t*)&o;
                }
            }
        }
    }
    // zero pad cols [200,224)
    for (int e = tid; e < MTILE * 12; e += 256) {
        int r = e / 12, cc = HID + (e % 12) * 2;
        *(uint32_t*)&Hs[r * HS_STRIDE + cc] = 0u;
    }

    #pragma unroll
    for (int mt = 0; mt < 2; ++mt)
        #pragma unroll
        for (int t = 0; t < 7; ++t)
            #pragma unroll
            for (int v = 0; v < 4; ++v) acc[mt][t][v] = 0.f;

    // ---------------- layer-2 prologue ----------------
    {
        #pragma unroll
        for (int u = 0; u < 4; ++u) {
            int e = tid + u * 256;
            if (e < HID * 4) {
                int n = e >> 2, seg = e & 3;
                cpasync16(ws_base[0] + n * (XS_STRIDE * 2) + seg * 16,
                          g_W2t + (size_t)n * K2PAD + seg * 8);
            }
        }
        cpasync_commit();
        cpasync_wait0();
        __syncthreads();            // covers Hs writes + W2(0)
    }
    // ---------------- layer-2 mainloop (A from Hs) ----------------
    for (int c = 0; c < L2C; ++c) {
        uint32_t wsb = ws_base[c & 1];
        int nb = (c + 1) & 1;
        if (c + 1 < L2C) {
            int c0n = (c + 1) * 32;
            #pragma unroll
            for (int u = 0; u < 4; ++u) {
                int e = tid + u * 256;
                if (e < HID * 4) {
                    int n = e >> 2, seg = e & 3;
                    cpasync16(ws_base[nb] + n * (XS_STRIDE * 2) + seg * 16,
                              g_W2t + (size_t)n * K2PAD + c0n + seg * 8);
                }
            }
            cpasync_commit();
        }
        int c0 = c * 32;
        #pragma unroll
        for (int ks = 0; ks < 2; ++ks) {
            int kb = ks * 16;
            uint32_t a[2][4];
            #pragma unroll
            for (int mt = 0; mt < 2; ++mt)
                ldsm_x4(a[mt], hs_base + ((rowA + mt * 16) * HS_STRIDE + c0 + kb + colhA) * 2);
            #pragma unroll
            for (int t = 0; t < 7; ++t) {
                int nt_g = wn + 4 * t;
                if (nt_g < NTILES) {
                    uint32_t bb[2];
                    ldsm_x2(bb, wsb + ((nt_g * 8 + rowB) * XS_STRIDE + kb + colhB) * 2);
                    #pragma unroll
                    for (int mt = 0; mt < 2; ++mt)
                        mma16816(acc[mt][t], a[mt], bb);
                }
            }
        }
        if (c + 1 < L2C) cpasync_wait0();
        __syncthreads();
    }

    // ---------------- scoring epilogue ----------------
    #pragma unroll
    for (int mt = 0; mt < 2; ++mt) {
        #pragma unroll
        for (int half = 0; half < 2; ++half) {
            float sp = 0.f;
            #pragma unroll
            for (int t = 0; t < 7; ++t) {
                int nt_g = wn + 4 * t;
                if (nt_g < NTILES) {
                    int col = nt_g * 8 + 2 * l4;
                    float h0 = fmaxf(acc[mt][t][half * 2 + 0] + b2s[col], 0.f);
                    float h1 = fmaxf(acc[mt][t][half * 2 + 1] + b2s[col + 1], 0.f);
                    sp = fmaf(h0, W3s[col], sp);
                    sp = fmaf(h1, W3s[col + 1], sp);
                }
            }
            sp += __shfl_xor_sync(0xFFFFFFFFu, sp, 1);
            sp += __shfl_xor_sync(0xFFFFFFFFu, sp, 2);
            if (l4 == 0) {
                int r = wm * 32 + mt * 16 + q + 8 * half;
                sred[r][wn] = sp;
            }
        }
    }
    __syncthreads();
    if (tid < MTILE) {
        float s = sred[tid][0] + sred[tid][1] + sred[tid][2] + sred[tid][3] + b3[0];
        int i = bi * 8 + (tid >> 3), j = bj * 8 + (tid & 7);
        if (i > j)
            g_S[((size_t)b * NSEL + i) * NSEL + j] = s;
    }
}

// ---------------- row softmax + fill ----------------
__global__ void k_soft(float* __restrict__ out) {
    int bn = blockIdx.x;
    int i = bn % NSEL;
    const float* Srow = g_S + (size_t)bn * NSEL;
    float* orow = out + (size_t)bn * NSEL;
    __shared__ float red[256];
    int tid = threadIdx.x;

    float mx = -1e30f;
    for (int j = tid; j <= i; j += 256) {
        float l = (j == i) ? 0.f : Srow[j];
        mx = fmaxf(mx, l);
    }
    red[tid] = mx; __syncthreads();
    for (int s = 128; s > 0; s >>= 1) {
        if (tid < s) red[tid] = fmaxf(red[tid], red[tid + s]);
        __syncthreads();
    }
    mx = red[0]; __syncthreads();

    float sum = 0.f;
    for (int j = tid; j <= i; j += 256) {
        float l = (j == i) ? 0.f : Srow[j];
        sum += __expf(l - mx);
    }
    red[tid] = sum; __syncthreads();
    for (int s = 128; s > 0; s >>= 1) {
        if (tid < s) red[tid] += red[tid + s];
        __syncthreads();
    }
    sum = red[0];
    float inv = 1.0f / sum;

    for (int j = tid; j < NSEL; j += 256) {
        if (j <= i) {
            float l = (j == i) ? 0.f : Srow[j];
            orow[j] = __expf(l - mx) * inv;
        } else {
            orow[j] = -1000.0f;
        }
    }
}

// ---------------- launch ----------------
extern "C" void kernel_launch(void* const* d_in, const int* in_sizes, int n_in,
                              void* d_out, int out_size) {
    const float* emb = (const float*)d_in[0];
    const int*   idx = (const int*)  d_in[1];
    const float* W1  = (const float*)d_in[2];
    const float* b1  = (const float*)d_in[3];
    const float* W2  = (const float*)d_in[4];
    const float* b2  = (const float*)d_in[5];
    const float* W3  = (const float*)d_in[6];
    const float* b3  = (const float*)d_in[7];
    float* out = (float*)d_out;

    static int configured = 0;
    if (!configured) {
        cudaFuncSetAttribute(k_fused, cudaFuncAttributeMaxDynamicSharedMemorySize,
                             DYN_BYTES);
        configured = 1;
    }

    k_prep<<<PREP_BLKS, 256>>>(emb, idx, W1, W2);
    k_ab<<<dim3(16, 7), 256>>>(W1);
    k_fused<<<dim3(NBLK, BATCH), 256, DYN_BYTES>>>(b1, b2, W3, b3);
    k_soft<<<BATCH * NSEL, 256>>>(out);
}